// round 7
// baseline (speedup 1.0000x reference)
#include <cuda_runtime.h>
#include <cstdint>
#include <math_constants.h>

// ---------------------------------------------------------------------------
// AdaptiveAttention: B=2, S=2048, HS=1024, NH=16, HD=64, NP=8
// Round 7: 3xTF32 mma.sync with hoisted (store-time) operand splitting +
//          merged QKV projection launch.
// ---------------------------------------------------------------------------

constexpr int cB = 2, cS = 2048, cHS = 1024, cNH = 16, cNP = 8, cHD = 64;
constexpr float cSCALE = 0.125f;  // 1/sqrt(64)
constexpr long OUT_ELEMS  = (long)cB * cS * cHS;        // 4,194,304
constexpr long ATTN_ELEMS = (long)cB * cNH * cS * cS;   // 134,217,728

__device__ float g_Q[(long)cB * cNH * cS * cHD];
__device__ float g_K[(long)cB * cNH * cS * cHD];
__device__ float g_V[(long)cB * cNH * cS * cHD];     // [b,h,s,d]
__device__ float g_ctx[(long)cB * cS * cHS];
__device__ float g_pat[cB * cNH];
__device__ float g_WT[4L * cHS * cHS];               // transposed weights [N,K] x4
__device__ float g_qpart[32 * cHS];
__device__ float g_attn_fallback[ATTN_ELEMS];

// ---------------------------------------------------------------------------
__device__ __forceinline__ void mma_tf32(float c[4], const uint32_t a[4], const uint32_t b[2]) {
    asm volatile(
        "mma.sync.aligned.m16n8k8.row.col.f32.tf32.tf32.f32 "
        "{%0,%1,%2,%3}, {%4,%5,%6,%7}, {%8,%9}, {%0,%1,%2,%3};"
        : "+f"(c[0]), "+f"(c[1]), "+f"(c[2]), "+f"(c[3])
        : "r"(a[0]), "r"(a[1]), "r"(a[2]), "r"(a[3]), "r"(b[0]), "r"(b[1]));
}

// 3xTF32 split: x = hi + lo (both tf32-representable).
__device__ __forceinline__ void splitf(float x, float& hi, float& lo) {
    uint32_t h, l;
    asm("cvt.rna.tf32.f32 %0, %1;" : "=r"(h) : "f"(x));
    float r = x - __uint_as_float(h);
    asm("cvt.rna.tf32.f32 %0, %1;" : "=r"(l) : "f"(r));
    hi = __uint_as_float(h);
    lo = __uint_as_float(l);
}
__device__ __forceinline__ void split4(float4 v, float4& hi, float4& lo) {
    splitf(v.x, hi.x, lo.x); splitf(v.y, hi.y, lo.y);
    splitf(v.z, hi.z, lo.z); splitf(v.w, hi.w, lo.w);
}

// ===========================================================================
// QKV projection (merged): C_z = A_z[4096,1024] @ WT_z^T + bias_z,
// scattered to [B,NH,S,HD]. Block 128x128, K-chunk 32, double buffered,
// hi/lo pre-split smem. 8 warps 4(m) x 2(n).
// ===========================================================================
__global__ __launch_bounds__(256)
void gemm_qkv(const float* __restrict__ Aq, const float* __restrict__ Ak,
              const float* __restrict__ Av, const float* __restrict__ WT,
              const float* __restrict__ bq, const float* __restrict__ bk,
              const float* __restrict__ bv,
              float* __restrict__ Cq, float* __restrict__ Ck, float* __restrict__ Cv)
{
    extern __shared__ float sm[];
    float* Ah = sm;               // [2][128*36]
    float* Al = sm + 2 * 4608;
    float* Bh = sm + 4 * 4608;
    float* Bl = sm + 6 * 4608;
    const int z = blockIdx.z;
    const float* A    = z == 0 ? Aq : (z == 1 ? Ak : Av);
    const float* Bt   = WT + (size_t)z * cHS * cHS;
    const float* bias = z == 0 ? bq : (z == 1 ? bk : bv);
    float* C          = z == 0 ? Cq : (z == 1 ? Ck : Cv);

    const int t = threadIdx.x, lane = t & 31, wid = t >> 5;
    const int wm = wid >> 1, wn = wid & 1;
    const int gid = lane >> 2, tig = lane & 3;
    const int m0 = blockIdx.y * 128, n0 = blockIdx.x * 128;

    float c[2][8][4] = {};
    float4 rA[4], rB[4];

    // chunk 0: load + split + store
#pragma unroll
    for (int i = 0; i < 4; i++) {
        int idx = t + i * 256, r = idx >> 3, kq = idx & 7;
        rA[i] = *(const float4*)&A[(size_t)(m0 + r) * 1024 + kq * 4];
        rB[i] = *(const float4*)&Bt[(size_t)(n0 + r) * 1024 + kq * 4];
    }
#pragma unroll
    for (int i = 0; i < 4; i++) {
        int idx = t + i * 256, r = idx >> 3, kq = idx & 7;
        float4 h, l;
        split4(rA[i], h, l);
        *(float4*)&Ah[r * 36 + kq * 4] = h;
        *(float4*)&Al[r * 36 + kq * 4] = l;
        split4(rB[i], h, l);
        *(float4*)&Bh[r * 36 + kq * 4] = h;
        *(float4*)&Bl[r * 36 + kq * 4] = l;
    }
    __syncthreads();

    const int T = 32;
    for (int ch = 0; ch < T; ch++) {
        const int cur = ch & 1;
        if (ch + 1 < T) {
#pragma unroll
            for (int i = 0; i < 4; i++) {
                int idx = t + i * 256, r = idx >> 3, kq = idx & 7;
                rA[i] = *(const float4*)&A[(size_t)(m0 + r) * 1024 + (ch + 1) * 32 + kq * 4];
                rB[i] = *(const float4*)&Bt[(size_t)(n0 + r) * 1024 + (ch + 1) * 32 + kq * 4];
            }
        }
        const float* Ahb = Ah + cur * 4608;
        const float* Alb = Al + cur * 4608;
        const float* Bhb = Bh + cur * 4608;
        const float* Blb = Bl + cur * 4608;
#pragma unroll
        for (int kk = 0; kk < 4; kk++) {
            uint32_t ah[2][4], al[2][4], bh[8][2], bl[8][2];
#pragma unroll
            for (int mi = 0; mi < 2; mi++) {
                int r = wm * 32 + mi * 16 + gid;
                int o0 = r * 36 + kk * 8 + tig, o1 = (r + 8) * 36 + kk * 8 + tig;
                ah[mi][0] = __float_as_uint(Ahb[o0]);
                ah[mi][1] = __float_as_uint(Ahb[o1]);
                ah[mi][2] = __float_as_uint(Ahb[o0 + 4]);
                ah[mi][3] = __float_as_uint(Ahb[o1 + 4]);
                al[mi][0] = __float_as_uint(Alb[o0]);
                al[mi][1] = __float_as_uint(Alb[o1]);
                al[mi][2] = __float_as_uint(Alb[o0 + 4]);
                al[mi][3] = __float_as_uint(Alb[o1 + 4]);
            }
#pragma unroll
            for (int ni = 0; ni < 8; ni++) {
                int n = wn * 64 + ni * 8 + gid;
                int o = n * 36 + kk * 8 + tig;
                bh[ni][0] = __float_as_uint(Bhb[o]);
                bh[ni][1] = __float_as_uint(Bhb[o + 4]);
                bl[ni][0] = __float_as_uint(Blb[o]);
                bl[ni][1] = __float_as_uint(Blb[o + 4]);
            }
#pragma unroll
            for (int mi = 0; mi < 2; mi++)
#pragma unroll
                for (int ni = 0; ni < 8; ni++) {
                    mma_tf32(c[mi][ni], al[mi], bh[ni]);
                    mma_tf32(c[mi][ni], ah[mi], bl[ni]);
                    mma_tf32(c[mi][ni], ah[mi], bh[ni]);
                }
        }
        if (ch + 1 < T) {
            __syncthreads();
            float* Ahw = Ah + (cur ^ 1) * 4608;
            float* Alw = Al + (cur ^ 1) * 4608;
            float* Bhw = Bh + (cur ^ 1) * 4608;
            float* Blw = Bl + (cur ^ 1) * 4608;
#pragma unroll
            for (int i = 0; i < 4; i++) {
                int idx = t + i * 256, r = idx >> 3, kq = idx & 7;
                float4 h, l;
                split4(rA[i], h, l);
                *(float4*)&Ahw[r * 36 + kq * 4] = h;
                *(float4*)&Alw[r * 36 + kq * 4] = l;
                split4(rB[i], h, l);
                *(float4*)&Bhw[r * 36 + kq * 4] = h;
                *(float4*)&Blw[r * 36 + kq * 4] = l;
            }
            __syncthreads();
        }
    }

#pragma unroll
    for (int mi = 0; mi < 2; mi++)
#pragma unroll
        for (int half = 0; half < 2; half++) {
            int m = m0 + wm * 32 + mi * 16 + gid + half * 8;
            int b = m >> 11, s = m & 2047;
#pragma unroll
            for (int ni = 0; ni < 8; ni++) {
                int n = n0 + wn * 64 + ni * 8 + tig * 2;
                float2 v;
                v.x = c[mi][ni][half * 2 + 0] + bias[n];
                v.y = c[mi][ni][half * 2 + 1] + bias[n + 1];
                int h = n >> 6, d = n & 63;
                *(float2*)&C[(((size_t)(b * cNH + h) * cS + s) * cHD) + d] = v;
            }
        }
}

// ===========================================================================
// Output projection: C = ctx[4096,1024] @ WoT^T + bo, row-major store.
// ===========================================================================
__global__ __launch_bounds__(256)
void gemm_out(const float* __restrict__ A, const float* __restrict__ Bt,
              const float* __restrict__ bias, float* __restrict__ C)
{
    extern __shared__ float sm[];
    float* Ah = sm;
    float* Al = sm + 2 * 4608;
    float* Bh = sm + 4 * 4608;
    float* Bl = sm + 6 * 4608;
    const int t = threadIdx.x, lane = t & 31, wid = t >> 5;
    const int wm = wid >> 1, wn = wid & 1;
    const int gid = lane >> 2, tig = lane & 3;
    const int m0 = blockIdx.y * 128, n0 = blockIdx.x * 128;

    float c[2][8][4] = {};
    float4 rA[4], rB[4];

#pragma unroll
    for (int i = 0; i < 4; i++) {
        int idx = t + i * 256, r = idx >> 3, kq = idx & 7;
        rA[i] = *(const float4*)&A[(size_t)(m0 + r) * 1024 + kq * 4];
        rB[i] = *(const float4*)&Bt[(size_t)(n0 + r) * 1024 + kq * 4];
    }
#pragma unroll
    for (int i = 0; i < 4; i++) {
        int idx = t + i * 256, r = idx >> 3, kq = idx & 7;
        float4 h, l;
        split4(rA[i], h, l);
        *(float4*)&Ah[r * 36 + kq * 4] = h;
        *(float4*)&Al[r * 36 + kq * 4] = l;
        split4(rB[i], h, l);
        *(float4*)&Bh[r * 36 + kq * 4] = h;
        *(float4*)&Bl[r * 36 + kq * 4] = l;
    }
    __syncthreads();

    const int T = 32;
    for (int ch = 0; ch < T; ch++) {
        const int cur = ch & 1;
        if (ch + 1 < T) {
#pragma unroll
            for (int i = 0; i < 4; i++) {
                int idx = t + i * 256, r = idx >> 3, kq = idx & 7;
                rA[i] = *(const float4*)&A[(size_t)(m0 + r) * 1024 + (ch + 1) * 32 + kq * 4];
                rB[i] = *(const float4*)&Bt[(size_t)(n0 + r) * 1024 + (ch + 1) * 32 + kq * 4];
            }
        }
        const float* Ahb = Ah + cur * 4608;
        const float* Alb = Al + cur * 4608;
        const float* Bhb = Bh + cur * 4608;
        const float* Blb = Bl + cur * 4608;
#pragma unroll
        for (int kk = 0; kk < 4; kk++) {
            uint32_t ah[2][4], al[2][4], bh[8][2], bl[8][2];
#pragma unroll
            for (int mi = 0; mi < 2; mi++) {
                int r = wm * 32 + mi * 16 + gid;
                int o0 = r * 36 + kk * 8 + tig, o1 = (r + 8) * 36 + kk * 8 + tig;
                ah[mi][0] = __float_as_uint(Ahb[o0]);
                ah[mi][1] = __float_as_uint(Ahb[o1]);
                ah[mi][2] = __float_as_uint(Ahb[o0 + 4]);
                ah[mi][3] = __float_as_uint(Ahb[o1 + 4]);
                al[mi][0] = __float_as_uint(Alb[o0]);
                al[mi][1] = __float_as_uint(Alb[o1]);
                al[mi][2] = __float_as_uint(Alb[o0 + 4]);
                al[mi][3] = __float_as_uint(Alb[o1 + 4]);
            }
#pragma unroll
            for (int ni = 0; ni < 8; ni++) {
                int n = wn * 64 + ni * 8 + gid;
                int o = n * 36 + kk * 8 + tig;
                bh[ni][0] = __float_as_uint(Bhb[o]);
                bh[ni][1] = __float_as_uint(Bhb[o + 4]);
                bl[ni][0] = __float_as_uint(Blb[o]);
                bl[ni][1] = __float_as_uint(Blb[o + 4]);
            }
#pragma unroll
            for (int mi = 0; mi < 2; mi++)
#pragma unroll
                for (int ni = 0; ni < 8; ni++) {
                    mma_tf32(c[mi][ni], al[mi], bh[ni]);
                    mma_tf32(c[mi][ni], ah[mi], bl[ni]);
                    mma_tf32(c[mi][ni], ah[mi], bh[ni]);
                }
        }
        if (ch + 1 < T) {
            __syncthreads();
            float* Ahw = Ah + (cur ^ 1) * 4608;
            float* Alw = Al + (cur ^ 1) * 4608;
            float* Bhw = Bh + (cur ^ 1) * 4608;
            float* Blw = Bl + (cur ^ 1) * 4608;
#pragma unroll
            for (int i = 0; i < 4; i++) {
                int idx = t + i * 256, r = idx >> 3, kq = idx & 7;
                float4 h, l;
                split4(rA[i], h, l);
                *(float4*)&Ahw[r * 36 + kq * 4] = h;
                *(float4*)&Alw[r * 36 + kq * 4] = l;
                split4(rB[i], h, l);
                *(float4*)&Bhw[r * 36 + kq * 4] = h;
                *(float4*)&Blw[r * 36 + kq * 4] = l;
            }
            __syncthreads();
        }
    }

#pragma unroll
    for (int mi = 0; mi < 2; mi++)
#pragma unroll
        for (int half = 0; half < 2; half++) {
            int m = m0 + wm * 32 + mi * 16 + gid + half * 8;
#pragma unroll
            for (int ni = 0; ni < 8; ni++) {
                int n = n0 + wn * 64 + ni * 8 + tig * 2;
                float2 v;
                v.x = c[mi][ni][half * 2 + 0] + bias[n];
                v.y = c[mi][ni][half * 2 + 1] + bias[n + 1];
                *(float2*)&C[(size_t)m * 1024 + n] = v;
            }
        }
}

// ===========================================================================
// scores_mma: attn[bh,q,k] = (Q.K)*SCALE*pat, masked. 128x128 tile, K=64,
// one-shot with hi/lo pre-split smem (stride 68).
// ===========================================================================
__global__ __launch_bounds__(256)
void scores_mma(const int* __restrict__ mask, float* __restrict__ attn)
{
    extern __shared__ float sm[];
    float* Qh = sm;               // 128*68
    float* Ql = sm + 8704;
    float* Kh = sm + 2 * 8704;
    float* Kl = sm + 3 * 8704;
    const int t = threadIdx.x, lane = t & 31, wid = t >> 5;
    const int wm = wid >> 1, wn = wid & 1;
    const int gid = lane >> 2, tig = lane & 3;
    const int bh = blockIdx.z, b = bh >> 4;
    const int q0 = blockIdx.y * 128, n0 = blockIdx.x * 128;
    const float* Qm = g_Q + (size_t)bh * cS * cHD;
    const float* Km = g_K + (size_t)bh * cS * cHD;

#pragma unroll
    for (int i = 0; i < 8; i++) {
        int idx = t + i * 256, r = idx >> 4, kq = idx & 15;
        float4 v = *(const float4*)&Qm[(size_t)(q0 + r) * 64 + kq * 4];
        float4 h, l;
        split4(v, h, l);
        *(float4*)&Qh[r * 68 + kq * 4] = h;
        *(float4*)&Ql[r * 68 + kq * 4] = l;
        v = *(const float4*)&Km[(size_t)(n0 + r) * 64 + kq * 4];
        split4(v, h, l);
        *(float4*)&Kh[r * 68 + kq * 4] = h;
        *(float4*)&Kl[r * 68 + kq * 4] = l;
    }
    __syncthreads();

    float c[2][8][4] = {};
#pragma unroll
    for (int kk = 0; kk < 8; kk++) {
        uint32_t ah[2][4], al[2][4], bh[8][2], bl[8][2];
#pragma unroll
        for (int mi = 0; mi < 2; mi++) {
            int r = wm * 32 + mi * 16 + gid;
            int o0 = r * 68 + kk * 8 + tig, o1 = (r + 8) * 68 + kk * 8 + tig;
            ah[mi][0] = __float_as_uint(Qh[o0]);
            ah[mi][1] = __float_as_uint(Qh[o1]);
            ah[mi][2] = __float_as_uint(Qh[o0 + 4]);
            ah[mi][3] = __float_as_uint(Qh[o1 + 4]);
            al[mi][0] = __float_as_uint(Ql[o0]);
            al[mi][1] = __float_as_uint(Ql[o1]);
            al[mi][2] = __float_as_uint(Ql[o0 + 4]);
            al[mi][3] = __float_as_uint(Ql[o1 + 4]);
        }
#pragma unroll
        for (int ni = 0; ni < 8; ni++) {
            int n = wn * 64 + ni * 8 + gid;
            int o = n * 68 + kk * 8 + tig;
            bh[ni][0] = __float_as_uint(Kh[o]);
            bh[ni][1] = __float_as_uint(Kh[o + 4]);
            bl[ni][0] = __float_as_uint(Kl[o]);
            bl[ni][1] = __float_as_uint(Kl[o + 4]);
        }
#pragma unroll
        for (int mi = 0; mi < 2; mi++)
#pragma unroll
            for (int ni = 0; ni < 8; ni++) {
                mma_tf32(c[mi][ni], al[mi], bh[ni]);
                mma_tf32(c[mi][ni], ah[mi], bl[ni]);
                mma_tf32(c[mi][ni], ah[mi], bh[ni]);
            }
    }

    const float patv = g_pat[bh] * cSCALE;
    const size_t mbase = (size_t)b * cS * cS;
    const size_t abase = (size_t)bh * cS * cS;
#pragma unroll
    for (int mi = 0; mi < 2; mi++)
#pragma unroll
        for (int half = 0; half < 2; half++) {
            int q = q0 + wm * 32 + mi * 16 + gid + half * 8;
#pragma unroll
            for (int ni = 0; ni < 8; ni++) {
                int col = n0 + wn * 64 + ni * 8 + tig * 2;
                float2 v;
                v.x = c[mi][ni][half * 2 + 0] * patv;
                v.y = c[mi][ni][half * 2 + 1] * patv;
                int2 mk = *(const int2*)&mask[mbase + (size_t)q * cS + col];
                if (mk.x == 0) v.x = -1e9f;
                if (mk.y == 0) v.y = -1e9f;
                *(float2*)&attn[abase + (size_t)q * cS + col] = v;
            }
        }
}

// ===========================================================================
// context_mma: ctx = attn @ V, block 128x64, K=2048 (32-chunks, double
// buffered, hi/lo pre-split). 8 warps 4x2, warp tile 32x32.
// ===========================================================================
__global__ __launch_bounds__(256)
void context_mma(const float* __restrict__ attn)
{
    extern __shared__ float sm[];
    float* Ah = sm;                 // [2][128*36]
    float* Al = sm + 2 * 4608;
    float* Bh = sm + 4 * 4608;      // [2][64*36]
    float* Bl = sm + 4 * 4608 + 2 * 2304;
    const int t = threadIdx.x, lane = t & 31, wid = t >> 5;
    const int wm = wid >> 1, wn = wid & 1;
    const int gid = lane >> 2, tig = lane & 3;
    const int bh = blockIdx.y, q0 = blockIdx.x * 128;
    const int b = bh >> 4, h = bh & 15;
    const float* Am = attn + (size_t)bh * cS * cS;
    const float* Vm = g_V + (size_t)bh * cS * cHD;

    float c[2][4][4] = {};
    float4 rA[4], rB[2];

#pragma unroll
    for (int i = 0; i < 4; i++) {
        int idx = t + i * 256, r = idx >> 3, kq = idx & 7;
        rA[i] = *(const float4*)&Am[(size_t)(q0 + r) * cS + kq * 4];
    }
#pragma unroll
    for (int i = 0; i < 2; i++) {
        int idx = t + i * 256, sl = idx >> 4, dq = idx & 15;
        rB[i] = *(const float4*)&Vm[(size_t)sl * 64 + dq * 4];
    }
#pragma unroll
    for (int i = 0; i < 4; i++) {
        int idx = t + i * 256, r = idx >> 3, kq = idx & 7;
        float4 hh, ll;
        split4(rA[i], hh, ll);
        *(float4*)&Ah[r * 36 + kq * 4] = hh;
        *(float4*)&Al[r * 36 + kq * 4] = ll;
    }
#pragma unroll
    for (int i = 0; i < 2; i++) {
        int idx = t + i * 256, sl = idx >> 4, dq = idx & 15;
        float4 hh, ll;
        split4(rB[i], hh, ll);
        Bh[(dq * 4 + 0) * 36 + sl] = hh.x; Bl[(dq * 4 + 0) * 36 + sl] = ll.x;
        Bh[(dq * 4 + 1) * 36 + sl] = hh.y; Bl[(dq * 4 + 1) * 36 + sl] = ll.y;
        Bh[(dq * 4 + 2) * 36 + sl] = hh.z; Bl[(dq * 4 + 2) * 36 + sl] = ll.z;
        Bh[(dq * 4 + 3) * 36 + sl] = hh.w; Bl[(dq * 4 + 3) * 36 + sl] = ll.w;
    }
    __syncthreads();

    const int T = 64;
    for (int ch = 0; ch < T; ch++) {
        const int cur = ch & 1;
        if (ch + 1 < T) {
#pragma unroll
            for (int i = 0; i < 4; i++) {
                int idx = t + i * 256, r = idx >> 3, kq = idx & 7;
                rA[i] = *(const float4*)&Am[(size_t)(q0 + r) * cS + (ch + 1) * 32 + kq * 4];
            }
#pragma unroll
            for (int i = 0; i < 2; i++) {
                int idx = t + i * 256, sl = idx >> 4, dq = idx & 15;
                rB[i] = *(const float4*)&Vm[(size_t)((ch + 1) * 32 + sl) * 64 + dq * 4];
            }
        }
        const float* Ahb = Ah + cur * 4608;
        const float* Alb = Al + cur * 4608;
        const float* Bhb = Bh + cur * 2304;
        const float* Blb = Bl + cur * 2304;
#pragma unroll
        for (int kk = 0; kk < 4; kk++) {
            uint32_t ah[2][4], al[2][4], bh2[4][2], bl2[4][2];
#pragma unroll
            for (int mi = 0; mi < 2; mi++) {
                int r = wm * 32 + mi * 16 + gid;
                int o0 = r * 36 + kk * 8 + tig, o1 = (r + 8) * 36 + kk * 8 + tig;
                ah[mi][0] = __float_as_uint(Ahb[o0]);
                ah[mi][1] = __float_as_uint(Ahb[o1]);
                ah[mi][2] = __float_as_uint(Ahb[o0 + 4]);
                ah[mi][3] = __float_as_uint(Ahb[o1 + 4]);
                al[mi][0] = __float_as_uint(Alb[o0]);
                al[mi][1] = __float_as_uint(Alb[o1]);
                al[mi][2] = __float_as_uint(Alb[o0 + 4]);
                al[mi][3] = __float_as_uint(Alb[o1 + 4]);
            }
#pragma unroll
            for (int ni = 0; ni < 4; ni++) {
                int n = wn * 32 + ni * 8 + gid;
                int o = n * 36 + kk * 8 + tig;
                bh2[ni][0] = __float_as_uint(Bhb[o]);
                bh2[ni][1] = __float_as_uint(Bhb[o + 4]);
                bl2[ni][0] = __float_as_uint(Blb[o]);
                bl2[ni][1] = __float_as_uint(Blb[o + 4]);
            }
#pragma unroll
            for (int mi = 0; mi < 2; mi++)
#pragma unroll
                for (int ni = 0; ni < 4; ni++) {
                    mma_tf32(c[mi][ni], al[mi], bh2[ni]);
                    mma_tf32(c[mi][ni], ah[mi], bl2[ni]);
                    mma_tf32(c[mi][ni], ah[mi], bh2[ni]);
                }
        }
        if (ch + 1 < T) {
            __syncthreads();
            float* Ahw = Ah + (cur ^ 1) * 4608;
            float* Alw = Al + (cur ^ 1) * 4608;
            float* Bhw = Bh + (cur ^ 1) * 2304;
            float* Blw = Bl + (cur ^ 1) * 2304;
#pragma unroll
            for (int i = 0; i < 4; i++) {
                int idx = t + i * 256, r = idx >> 3, kq = idx & 7;
                float4 hh, ll;
                split4(rA[i], hh, ll);
                *(float4*)&Ahw[r * 36 + kq * 4] = hh;
                *(float4*)&Alw[r * 36 + kq * 4] = ll;
            }
#pragma unroll
            for (int i = 0; i < 2; i++) {
                int idx = t + i * 256, sl = idx >> 4, dq = idx & 15;
                float4 hh, ll;
                split4(rB[i], hh, ll);
                Bhw[(dq * 4 + 0) * 36 + sl] = hh.x; Blw[(dq * 4 + 0) * 36 + sl] = ll.x;
                Bhw[(dq * 4 + 1) * 36 + sl] = hh.y; Blw[(dq * 4 + 1) * 36 + sl] = ll.y;
                Bhw[(dq * 4 + 2) * 36 + sl] = hh.z; Blw[(dq * 4 + 2) * 36 + sl] = ll.z;
                Bhw[(dq * 4 + 3) * 36 + sl] = hh.w; Blw[(dq * 4 + 3) * 36 + sl] = ll.w;
            }
            __syncthreads();
        }
    }

#pragma unroll
    for (int mi = 0; mi < 2; mi++)
#pragma unroll
        for (int half = 0; half < 2; half++) {
            int s = q0 + wm * 32 + mi * 16 + gid + half * 8;
#pragma unroll
            for (int ni = 0; ni < 4; ni++) {
                int n = wn * 32 + ni * 8 + tig * 2;
                float2 v;
                v.x = c[mi][ni][half * 2 + 0];
                v.y = c[mi][ni][half * 2 + 1];
                *(float2*)&g_ctx[((size_t)(b * cS + s)) * cHS + h * cHD + n] = v;
            }
        }
}

// ===========================================================================
// Softmax over rows of attn (S=2048), float4 vectorized.
// ===========================================================================
__global__ __launch_bounds__(256)
void softmax_k(float* __restrict__ attn)
{
    const size_t row = blockIdx.x;
    float4* p = (float4*)(attn + row * cS);
    const int t = threadIdx.x;
    float4 v0 = p[t], v1 = p[t + 256];
    float mx = fmaxf(fmaxf(fmaxf(v0.x, v0.y), fmaxf(v0.z, v0.w)),
                     fmaxf(fmaxf(v1.x, v1.y), fmaxf(v1.z, v1.w)));
    __shared__ float red[8];
#pragma unroll
    for (int o = 16; o > 0; o >>= 1) mx = fmaxf(mx, __shfl_xor_sync(0xffffffff, mx, o));
    if ((t & 31) == 0) red[t >> 5] = mx;
    __syncthreads();
    mx = fmaxf(fmaxf(fmaxf(red[0], red[1]), fmaxf(red[2], red[3])),
               fmaxf(fmaxf(red[4], red[5]), fmaxf(red[6], red[7])));
    v0.x = __expf(v0.x - mx); v0.y = __expf(v0.y - mx);
    v0.z = __expf(v0.z - mx); v0.w = __expf(v0.w - mx);
    v1.x = __expf(v1.x - mx); v1.y = __expf(v1.y - mx);
    v1.z = __expf(v1.z - mx); v1.w = __expf(v1.w - mx);
    float sm = v0.x + v0.y + v0.z + v0.w + v1.x + v1.y + v1.z + v1.w;
#pragma unroll
    for (int o = 16; o > 0; o >>= 1) sm += __shfl_xor_sync(0xffffffff, sm, o);
    __shared__ float red2[8];
    if ((t & 31) == 0) red2[t >> 5] = sm;
    __syncthreads();
    sm = red2[0] + red2[1] + red2[2] + red2[3] + red2[4] + red2[5] + red2[6] + red2[7];
    float inv = 1.0f / sm;
    v0.x *= inv; v0.y *= inv; v0.z *= inv; v0.w *= inv;
    v1.x *= inv; v1.y *= inv; v1.z *= inv; v1.w *= inv;
    p[t] = v0; p[t + 256] = v1;
}

// ===========================================================================
// Weight transpose: g_WT[z][n][k] = W_z[k][n]
// ===========================================================================
__global__ void transpose_w(const float* __restrict__ W0, const float* __restrict__ W1,
                            const float* __restrict__ W2, const float* __restrict__ W3)
{
    __shared__ float tile[32][33];
    const float* W = blockIdx.z == 0 ? W0 : blockIdx.z == 1 ? W1 : blockIdx.z == 2 ? W2 : W3;
    float* O = g_WT + (size_t)blockIdx.z * cHS * cHS;
    int x = blockIdx.x * 32 + threadIdx.x;
    int y0 = blockIdx.y * 32;
#pragma unroll
    for (int i = 0; i < 4; i++)
        tile[threadIdx.y + i * 8][threadIdx.x] = W[(size_t)(y0 + threadIdx.y + i * 8) * cHS + x];
    __syncthreads();
    int nx = blockIdx.y * 32 + threadIdx.x;
    int ny0 = blockIdx.x * 32;
#pragma unroll
    for (int i = 0; i < 4; i++)
        O[(size_t)(ny0 + threadIdx.y + i * 8) * cHS + nx] = tile[threadIdx.x][threadIdx.y + i * 8];
}

// ===========================================================================
// Pattern selector (deterministic two-stage column mean)
// ===========================================================================
__global__ void qmean_partial(const float* __restrict__ query)
{
    const int b = blockIdx.y, tile = blockIdx.x;
    const int t = threadIdx.x;
    const int r0 = tile * 128;
    float s1 = 0.f, s2 = 0.f;
    for (int r = 0; r < 128; r++) {
        const float* base = query + ((size_t)b * cS + r0 + r) * cHS;
        s1 += base[t];
        s2 += base[t + 512];
    }
    g_qpart[(b * 16 + tile) * cHS + t] = s1;
    g_qpart[(b * 16 + tile) * cHS + t + 512] = s2;
}

__global__ __launch_bounds__(512)
void pattern_kernel(const float* __restrict__ Wp1, const float* __restrict__ bp1,
                    const float* __restrict__ Wp2, const float* __restrict__ bp2,
                    const float* __restrict__ patterns)
{
    const int b = blockIdx.x;
    const int t = threadIdx.x;
    __shared__ float qm[cHS];
    __shared__ float hb[cHS / 2];
    __shared__ float pw[cNP];
    for (int c = t; c < cHS; c += 512) {
        float s = 0.f;
        for (int p = 0; p < 16; p++) s += g_qpart[(b * 16 + p) * cHS + c];
        qm[c] = s * (1.0f / cS);
    }
    __syncthreads();
    {
        float a = bp1[t];
        for (int c = 0; c < cHS; c++) a += qm[c] * Wp1[c * (cHS / 2) + t];
        hb[t] = fmaxf(a, 0.f);
    }
    __syncthreads();
    __shared__ float lg[cNP];
    if (t < cNP) {
        float a = bp2[t];
        for (int j = 0; j < cHS / 2; j++) a += hb[j] * Wp2[j * cNP + t];
        lg[t] = a;
    }
    __syncthreads();
    if (t == 0) {
        float mx = lg[0];
        for (int p = 1; p < cNP; p++) mx = fmaxf(mx, lg[p]);
        float s = 0.f;
        for (int p = 0; p < cNP; p++) { pw[p] = __expf(lg[p] - mx); s += pw[p]; }
        float inv = 1.0f / s;
        for (int p = 0; p < cNP; p++) pw[p] *= inv;
    }
    __syncthreads();
    if (t < cNH) {
        float a = 0.f;
        for (int p = 0; p < cNP; p++) a += pw[p] * patterns[p * cNH + t];
        g_pat[b * cNH + t] = a;
    }
}

// ===========================================================================
// kernel_launch
// ===========================================================================
extern "C" void kernel_launch(void* const* d_in, const int* in_sizes, int n_in,
                              void* d_out, int out_size)
{
    const float* query = (const float*)d_in[0];
    const float* key   = (const float*)d_in[1];
    const float* value = (const float*)d_in[2];
    const int*   mask  = (const int*)d_in[3];
    const float* Wq  = (const float*)d_in[4];  const float* bq  = (const float*)d_in[5];
    const float* Wk  = (const float*)d_in[6];  const float* bk  = (const float*)d_in[7];
    const float* Wv  = (const float*)d_in[8];  const float* bv  = (const float*)d_in[9];
    const float* Wo  = (const float*)d_in[10]; const float* bo  = (const float*)d_in[11];
    const float* Wp1 = (const float*)d_in[12]; const float* bp1 = (const float*)d_in[13];
    const float* Wp2 = (const float*)d_in[14]; const float* bp2 = (const float*)d_in[15];
    const float* patterns = (const float*)d_in[16];
    float* out = (float*)d_out;

    void *pQ, *pK, *pV, *pCtx, *pWT;
    cudaGetSymbolAddress(&pQ, g_Q);
    cudaGetSymbolAddress(&pK, g_K);
    cudaGetSymbolAddress(&pV, g_V);
    cudaGetSymbolAddress(&pCtx, g_ctx);
    cudaGetSymbolAddress(&pWT, g_WT);
    const float* WT = (const float*)pWT;

    float* attn;
    if ((long)out_size >= OUT_ELEMS + ATTN_ELEMS) {
        attn = out + OUT_ELEMS;
    } else {
        void* pa;
        cudaGetSymbolAddress(&pa, g_attn_fallback);
        attn = (float*)pa;
    }

    const int SM_GEMM   = 8 * 4608 * 4;                 // 147456
    const int SM_SCORES = 4 * 8704 * 4;                 // 139264
    const int SM_CTX    = (4 * 4608 + 4 * 2304) * 4;    // 110592
    cudaFuncSetAttribute(gemm_qkv,   cudaFuncAttributeMaxDynamicSharedMemorySize, SM_GEMM);
    cudaFuncSetAttribute(gemm_out,   cudaFuncAttributeMaxDynamicSharedMemorySize, SM_GEMM);
    cudaFuncSetAttribute(scores_mma, cudaFuncAttributeMaxDynamicSharedMemorySize, SM_SCORES);
    cudaFuncSetAttribute(context_mma, cudaFuncAttributeMaxDynamicSharedMemorySize, SM_CTX);

    // 1. pattern selector
    qmean_partial<<<dim3(16, cB), 512>>>(query);
    pattern_kernel<<<cB, 512>>>(Wp1, bp1, Wp2, bp2, patterns);

    // 2. transpose weights (Wq, Wk, Wv, Wo)
    transpose_w<<<dim3(32, 32, 4), dim3(32, 8)>>>(Wq, Wk, Wv, Wo);

    // 3. merged QKV projection -> [B,NH,S,HD]
    dim3 gProj(cHS / 128, (cB * cS) / 128, 3);  // (8, 32, 3) = 768 CTAs
    gemm_qkv<<<gProj, 256, SM_GEMM>>>(query, key, value, WT, bq, bk, bv,
                                      (float*)pQ, (float*)pK, (float*)pV);

    // 4. scores
    dim3 gScores(cS / 128, cS / 128, cB * cNH);  // (16, 16, 32)
    scores_mma<<<gScores, 256, SM_SCORES>>>(mask, attn);

    // 5. softmax
    softmax_k<<<cB * cNH * cS, 256>>>(attn);

    // 6. context
    dim3 gCtx(cS / 128, cB * cNH);  // (16, 32)
    context_mma<<<gCtx, 256, SM_CTX>>>(attn);

    // 7. output projection
    dim3 gOut(cHS / 128, (cB * cS) / 128);
    gemm_out<<<gOut, 256, SM_GEMM>>>((const float*)pCtx, WT + 3L * cHS * cHS, bo, out);
}

// round 8
// speedup vs baseline: 1.3629x; 1.3629x over previous
#include <cuda_runtime.h>
#include <cuda_bf16.h>
#include <cstdint>
#include <math_constants.h>

// ---------------------------------------------------------------------------
// AdaptiveAttention: B=2, S=2048, HS=1024, NH=16, HD=64, NP=8
// Round 8: 3-term bf16 split mma.sync m16n8k16 (2x tensor rate vs tf32,
//          half the smem/LDS traffic). Merged QKV launch kept.
// ---------------------------------------------------------------------------

constexpr int cB = 2, cS = 2048, cHS = 1024, cNH = 16, cNP = 8, cHD = 64;
constexpr float cSCALE = 0.125f;  // 1/sqrt(64)
constexpr long OUT_ELEMS  = (long)cB * cS * cHS;        // 4,194,304
constexpr long ATTN_ELEMS = (long)cB * cNH * cS * cS;   // 134,217,728

__device__ float g_Q[(long)cB * cNH * cS * cHD];
__device__ float g_K[(long)cB * cNH * cS * cHD];
__device__ float g_V[(long)cB * cNH * cS * cHD];     // [b,h,s,d]
__device__ float g_ctx[(long)cB * cS * cHS];
__device__ float g_pat[cB * cNH];
__device__ float g_WT[4L * cHS * cHS];               // transposed weights [N,K] x4
__device__ float g_qpart[32 * cHS];
__device__ float g_attn_fallback[ATTN_ELEMS];

// ---------------------------------------------------------------------------
__device__ __forceinline__ void mma_bf16(float c[4], const uint32_t a[4], const uint32_t b[2]) {
    asm volatile(
        "mma.sync.aligned.m16n8k16.row.col.f32.bf16.bf16.f32 "
        "{%0,%1,%2,%3}, {%4,%5,%6,%7}, {%8,%9}, {%0,%1,%2,%3};"
        : "+f"(c[0]), "+f"(c[1]), "+f"(c[2]), "+f"(c[3])
        : "r"(a[0]), "r"(a[1]), "r"(a[2]), "r"(a[3]), "r"(b[0]), "r"(b[1]));
}

__device__ __forceinline__ uint32_t pk2(__nv_bfloat16 a, __nv_bfloat16 b) {
    __nv_bfloat162 t;
    t.x = a; t.y = b;           // a at low 16 bits = lower k
    return *(uint32_t*)&t;
}

// Split float4 (4 consecutive k) into packed bf16x2 hi/lo pairs.
__device__ __forceinline__ void split4_pk(float4 v, uint2& hp, uint2& lp) {
    __nv_bfloat16 h0 = __float2bfloat16_rn(v.x);
    __nv_bfloat16 h1 = __float2bfloat16_rn(v.y);
    __nv_bfloat16 h2 = __float2bfloat16_rn(v.z);
    __nv_bfloat16 h3 = __float2bfloat16_rn(v.w);
    __nv_bfloat16 l0 = __float2bfloat16_rn(v.x - __bfloat162float(h0));
    __nv_bfloat16 l1 = __float2bfloat16_rn(v.y - __bfloat162float(h1));
    __nv_bfloat16 l2 = __float2bfloat16_rn(v.z - __bfloat162float(h2));
    __nv_bfloat16 l3 = __float2bfloat16_rn(v.w - __bfloat162float(h3));
    hp.x = pk2(h0, h1); hp.y = pk2(h2, h3);
    lp.x = pk2(l0, l1); lp.y = pk2(l2, l3);
}

__device__ __forceinline__ void split1(float x, __nv_bfloat16& h, __nv_bfloat16& l) {
    h = __float2bfloat16_rn(x);
    l = __float2bfloat16_rn(x - __bfloat162float(h));
}

// ===========================================================================
// gemm_bf: C = A[4096,1024] @ Bt^T + bias (Bt is [N,K]).
// MODE 1: merged QKV via blockIdx.z, scatter to [B,NH,S,HD].
// MODE 0: single GEMM, row-major store.
// Block 128x128, K-chunk 32, double-buffered bf16 hi/lo smem (stride 40).
// 8 warps 4(m) x 2(n), warp tile 32x64.
// ===========================================================================
template <int MODE>
__global__ __launch_bounds__(256)
void gemm_bf(const float* __restrict__ A0, const float* __restrict__ A1,
             const float* __restrict__ A2, const float* __restrict__ WT,
             const float* __restrict__ b0v, const float* __restrict__ b1v,
             const float* __restrict__ b2v,
             float* __restrict__ C0, float* __restrict__ C1, float* __restrict__ C2)
{
    extern __shared__ char smraw[];
    __nv_bfloat16* Ah = (__nv_bfloat16*)smraw;        // [2][128*40]
    __nv_bfloat16* Al = Ah + 2 * 5120;
    __nv_bfloat16* Bh = Ah + 4 * 5120;
    __nv_bfloat16* Bl = Ah + 6 * 5120;
    const int z = (MODE == 1) ? blockIdx.z : 0;
    const float* A    = z == 0 ? A0 : (z == 1 ? A1 : A2);
    const float* Bt   = WT + (size_t)z * cHS * cHS;
    const float* bias = z == 0 ? b0v : (z == 1 ? b1v : b2v);
    float* C          = z == 0 ? C0 : (z == 1 ? C1 : C2);

    const int t = threadIdx.x, lane = t & 31, wid = t >> 5;
    const int wm = wid >> 1, wn = wid & 1;
    const int gid = lane >> 2, tig = lane & 3;
    const int m0 = blockIdx.y * 128, n0 = blockIdx.x * 128;

    float c[2][8][4] = {};
    float4 rA[4], rB[4];

    // chunk 0
#pragma unroll
    for (int i = 0; i < 4; i++) {
        int idx = t + i * 256, r = idx >> 3, kq = idx & 7;
        rA[i] = *(const float4*)&A[(size_t)(m0 + r) * 1024 + kq * 4];
        rB[i] = *(const float4*)&Bt[(size_t)(n0 + r) * 1024 + kq * 4];
    }
#pragma unroll
    for (int i = 0; i < 4; i++) {
        int idx = t + i * 256, r = idx >> 3, kq = idx & 7;
        uint2 hp, lp;
        split4_pk(rA[i], hp, lp);
        *(uint2*)&Ah[r * 40 + kq * 4] = hp;
        *(uint2*)&Al[r * 40 + kq * 4] = lp;
        split4_pk(rB[i], hp, lp);
        *(uint2*)&Bh[r * 40 + kq * 4] = hp;
        *(uint2*)&Bl[r * 40 + kq * 4] = lp;
    }
    __syncthreads();

    const int T = 32;
    for (int ch = 0; ch < T; ch++) {
        const int cur = ch & 1;
        if (ch + 1 < T) {
#pragma unroll
            for (int i = 0; i < 4; i++) {
                int idx = t + i * 256, r = idx >> 3, kq = idx & 7;
                rA[i] = *(const float4*)&A[(size_t)(m0 + r) * 1024 + (ch + 1) * 32 + kq * 4];
                rB[i] = *(const float4*)&Bt[(size_t)(n0 + r) * 1024 + (ch + 1) * 32 + kq * 4];
            }
        }
        const __nv_bfloat16* Ahb = Ah + cur * 5120;
        const __nv_bfloat16* Alb = Al + cur * 5120;
        const __nv_bfloat16* Bhb = Bh + cur * 5120;
        const __nv_bfloat16* Blb = Bl + cur * 5120;
#pragma unroll
        for (int kk = 0; kk < 2; kk++) {
            uint32_t ah[2][4], al[2][4], bh[8][2], bl[8][2];
#pragma unroll
            for (int mi = 0; mi < 2; mi++) {
                int r = wm * 32 + mi * 16 + gid;
                int o = r * 40 + kk * 16 + tig * 2;
                ah[mi][0] = *(const uint32_t*)&Ahb[o];
                ah[mi][1] = *(const uint32_t*)&Ahb[o + 320];
                ah[mi][2] = *(const uint32_t*)&Ahb[o + 8];
                ah[mi][3] = *(const uint32_t*)&Ahb[o + 328];
                al[mi][0] = *(const uint32_t*)&Alb[o];
                al[mi][1] = *(const uint32_t*)&Alb[o + 320];
                al[mi][2] = *(const uint32_t*)&Alb[o + 8];
                al[mi][3] = *(const uint32_t*)&Alb[o + 328];
            }
#pragma unroll
            for (int ni = 0; ni < 8; ni++) {
                int n = wn * 64 + ni * 8 + gid;
                int o = n * 40 + kk * 16 + tig * 2;
                bh[ni][0] = *(const uint32_t*)&Bhb[o];
                bh[ni][1] = *(const uint32_t*)&Bhb[o + 8];
                bl[ni][0] = *(const uint32_t*)&Blb[o];
                bl[ni][1] = *(const uint32_t*)&Blb[o + 8];
            }
#pragma unroll
            for (int mi = 0; mi < 2; mi++)
#pragma unroll
                for (int ni = 0; ni < 8; ni++) {
                    mma_bf16(c[mi][ni], al[mi], bh[ni]);
                    mma_bf16(c[mi][ni], ah[mi], bl[ni]);
                    mma_bf16(c[mi][ni], ah[mi], bh[ni]);
                }
        }
        if (ch + 1 < T) {
            __syncthreads();
            __nv_bfloat16* Ahw = Ah + (cur ^ 1) * 5120;
            __nv_bfloat16* Alw = Al + (cur ^ 1) * 5120;
            __nv_bfloat16* Bhw = Bh + (cur ^ 1) * 5120;
            __nv_bfloat16* Blw = Bl + (cur ^ 1) * 5120;
#pragma unroll
            for (int i = 0; i < 4; i++) {
                int idx = t + i * 256, r = idx >> 3, kq = idx & 7;
                uint2 hp, lp;
                split4_pk(rA[i], hp, lp);
                *(uint2*)&Ahw[r * 40 + kq * 4] = hp;
                *(uint2*)&Alw[r * 40 + kq * 4] = lp;
                split4_pk(rB[i], hp, lp);
                *(uint2*)&Bhw[r * 40 + kq * 4] = hp;
                *(uint2*)&Blw[r * 40 + kq * 4] = lp;
            }
            __syncthreads();
        }
    }

#pragma unroll
    for (int mi = 0; mi < 2; mi++)
#pragma unroll
        for (int half = 0; half < 2; half++) {
            int m = m0 + wm * 32 + mi * 16 + gid + half * 8;
            int b = m >> 11, s = m & 2047;
#pragma unroll
            for (int ni = 0; ni < 8; ni++) {
                int n = n0 + wn * 64 + ni * 8 + tig * 2;
                float2 v;
                v.x = c[mi][ni][half * 2 + 0] + bias[n];
                v.y = c[mi][ni][half * 2 + 1] + bias[n + 1];
                if (MODE == 0) {
                    *(float2*)&C[(size_t)m * 1024 + n] = v;
                } else {
                    int h = n >> 6, d = n & 63;
                    *(float2*)&C[(((size_t)(b * cNH + h) * cS + s) * cHD) + d] = v;
                }
            }
        }
}

// ===========================================================================
// scores_mma: attn[bh,q,k] = (Q.K)*SCALE*pat, masked. 128x128 tile, K=64,
// one-shot, bf16 hi/lo smem (stride 72).
// ===========================================================================
__global__ __launch_bounds__(256)
void scores_mma(const int* __restrict__ mask, float* __restrict__ attn)
{
    extern __shared__ char smraw[];
    __nv_bfloat16* Qh = (__nv_bfloat16*)smraw;    // 128*72 each
    __nv_bfloat16* Ql = Qh + 9216;
    __nv_bfloat16* Kh = Qh + 2 * 9216;
    __nv_bfloat16* Kl = Qh + 3 * 9216;
    const int t = threadIdx.x, lane = t & 31, wid = t >> 5;
    const int wm = wid >> 1, wn = wid & 1;
    const int gid = lane >> 2, tig = lane & 3;
    const int bh = blockIdx.z, b = bh >> 4;
    const int q0 = blockIdx.y * 128, n0 = blockIdx.x * 128;
    const float* Qm = g_Q + (size_t)bh * cS * cHD;
    const float* Km = g_K + (size_t)bh * cS * cHD;

#pragma unroll
    for (int i = 0; i < 8; i++) {
        int idx = t + i * 256, r = idx >> 4, kq = idx & 15;
        uint2 hp, lp;
        float4 v = *(const float4*)&Qm[(size_t)(q0 + r) * 64 + kq * 4];
        split4_pk(v, hp, lp);
        *(uint2*)&Qh[r * 72 + kq * 4] = hp;
        *(uint2*)&Ql[r * 72 + kq * 4] = lp;
        v = *(const float4*)&Km[(size_t)(n0 + r) * 64 + kq * 4];
        split4_pk(v, hp, lp);
        *(uint2*)&Kh[r * 72 + kq * 4] = hp;
        *(uint2*)&Kl[r * 72 + kq * 4] = lp;
    }
    __syncthreads();

    float c[2][8][4] = {};
#pragma unroll
    for (int kk = 0; kk < 4; kk++) {
        uint32_t ah[2][4], al[2][4], bh2[8][2], bl2[8][2];
#pragma unroll
        for (int mi = 0; mi < 2; mi++) {
            int r = wm * 32 + mi * 16 + gid;
            int o = r * 72 + kk * 16 + tig * 2;
            ah[mi][0] = *(const uint32_t*)&Qh[o];
            ah[mi][1] = *(const uint32_t*)&Qh[o + 576];
            ah[mi][2] = *(const uint32_t*)&Qh[o + 8];
            ah[mi][3] = *(const uint32_t*)&Qh[o + 584];
            al[mi][0] = *(const uint32_t*)&Ql[o];
            al[mi][1] = *(const uint32_t*)&Ql[o + 576];
            al[mi][2] = *(const uint32_t*)&Ql[o + 8];
            al[mi][3] = *(const uint32_t*)&Ql[o + 584];
        }
#pragma unroll
        for (int ni = 0; ni < 8; ni++) {
            int n = wn * 64 + ni * 8 + gid;
            int o = n * 72 + kk * 16 + tig * 2;
            bh2[ni][0] = *(const uint32_t*)&Kh[o];
            bh2[ni][1] = *(const uint32_t*)&Kh[o + 8];
            bl2[ni][0] = *(const uint32_t*)&Kl[o];
            bl2[ni][1] = *(const uint32_t*)&Kl[o + 8];
        }
#pragma unroll
        for (int mi = 0; mi < 2; mi++)
#pragma unroll
            for (int ni = 0; ni < 8; ni++) {
                mma_bf16(c[mi][ni], al[mi], bh2[ni]);
                mma_bf16(c[mi][ni], ah[mi], bl2[ni]);
                mma_bf16(c[mi][ni], ah[mi], bh2[ni]);
            }
    }

    const float patv = g_pat[bh] * cSCALE;
    const size_t mbase = (size_t)b * cS * cS;
    const size_t abase = (size_t)bh * cS * cS;
#pragma unroll
    for (int mi = 0; mi < 2; mi++)
#pragma unroll
        for (int half = 0; half < 2; half++) {
            int q = q0 + wm * 32 + mi * 16 + gid + half * 8;
#pragma unroll
            for (int ni = 0; ni < 8; ni++) {
                int col = n0 + wn * 64 + ni * 8 + tig * 2;
                float2 v;
                v.x = c[mi][ni][half * 2 + 0] * patv;
                v.y = c[mi][ni][half * 2 + 1] * patv;
                int2 mk = *(const int2*)&mask[mbase + (size_t)q * cS + col];
                if (mk.x == 0) v.x = -1e9f;
                if (mk.y == 0) v.y = -1e9f;
                *(float2*)&attn[abase + (size_t)q * cS + col] = v;
            }
        }
}

// ===========================================================================
// context_mma: ctx = attn @ V. Block 128x64, K=2048 (32-chunks, double
// buffered, bf16 hi/lo). 8 warps 4x2, warp tile 32x32. V transposed on load.
// ===========================================================================
__global__ __launch_bounds__(256)
void context_mma(const float* __restrict__ attn)
{
    extern __shared__ char smraw[];
    __nv_bfloat16* Ah = (__nv_bfloat16*)smraw;   // [2][128*40]
    __nv_bfloat16* Al = Ah + 2 * 5120;
    __nv_bfloat16* Bh = Ah + 4 * 5120;           // [2][64*40]
    __nv_bfloat16* Bl = Ah + 4 * 5120 + 2 * 2560;
    const int t = threadIdx.x, lane = t & 31, wid = t >> 5;
    const int wm = wid >> 1, wn = wid & 1;
    const int gid = lane >> 2, tig = lane & 3;
    const int bh = blockIdx.y, q0 = blockIdx.x * 128;
    const int b = bh >> 4, h = bh & 15;
    const float* Am = attn + (size_t)bh * cS * cS;
    const float* Vm = g_V + (size_t)bh * cS * cHD;

    float c[2][4][4] = {};
    float4 rA[4], rB[2];

#pragma unroll
    for (int i = 0; i < 4; i++) {
        int idx = t + i * 256, r = idx >> 3, kq = idx & 7;
        rA[i] = *(const float4*)&Am[(size_t)(q0 + r) * cS + kq * 4];
    }
#pragma unroll
    for (int i = 0; i < 2; i++) {
        int idx = t + i * 256, sl = idx >> 4, dq = idx & 15;
        rB[i] = *(const float4*)&Vm[(size_t)sl * 64 + dq * 4];
    }
#pragma unroll
    for (int i = 0; i < 4; i++) {
        int idx = t + i * 256, r = idx >> 3, kq = idx & 7;
        uint2 hp, lp;
        split4_pk(rA[i], hp, lp);
        *(uint2*)&Ah[r * 40 + kq * 4] = hp;
        *(uint2*)&Al[r * 40 + kq * 4] = lp;
    }
#pragma unroll
    for (int i = 0; i < 2; i++) {
        int idx = t + i * 256, sl = idx >> 4, dq = idx & 15;
        const float vv[4] = {rB[i].x, rB[i].y, rB[i].z, rB[i].w};
#pragma unroll
        for (int j = 0; j < 4; j++) {
            __nv_bfloat16 hh, ll;
            split1(vv[j], hh, ll);
            Bh[(dq * 4 + j) * 40 + sl] = hh;
            Bl[(dq * 4 + j) * 40 + sl] = ll;
        }
    }
    __syncthreads();

    const int T = 64;
    for (int ch = 0; ch < T; ch++) {
        const int cur = ch & 1;
        if (ch + 1 < T) {
#pragma unroll
            for (int i = 0; i < 4; i++) {
                int idx = t + i * 256, r = idx >> 3, kq = idx & 7;
                rA[i] = *(const float4*)&Am[(size_t)(q0 + r) * cS + (ch + 1) * 32 + kq * 4];
            }
#pragma unroll
            for (int i = 0; i < 2; i++) {
                int idx = t + i * 256, sl = idx >> 4, dq = idx & 15;
                rB[i] = *(const float4*)&Vm[(size_t)((ch + 1) * 32 + sl) * 64 + dq * 4];
            }
        }
        const __nv_bfloat16* Ahb = Ah + cur * 5120;
        const __nv_bfloat16* Alb = Al + cur * 5120;
        const __nv_bfloat16* Bhb = Bh + cur * 2560;
        const __nv_bfloat16* Blb = Bl + cur * 2560;
#pragma unroll
        for (int kk = 0; kk < 2; kk++) {
            uint32_t ah[2][4], al[2][4], bh2[4][2], bl2[4][2];
#pragma unroll
            for (int mi = 0; mi < 2; mi++) {
                int r = wm * 32 + mi * 16 + gid;
                int o = r * 40 + kk * 16 + tig * 2;
                ah[mi][0] = *(const uint32_t*)&Ahb[o];
                ah[mi][1] = *(const uint32_t*)&Ahb[o + 320];
                ah[mi][2] = *(const uint32_t*)&Ahb[o + 8];
                ah[mi][3] = *(const uint32_t*)&Ahb[o + 328];
                al[mi][0] = *(const uint32_t*)&Alb[o];
                al[mi][1] = *(const uint32_t*)&Alb[o + 320];
                al[mi][2] = *(const uint32_t*)&Alb[o + 8];
                al[mi][3] = *(const uint32_t*)&Alb[o + 328];
            }
#pragma unroll
            for (int ni = 0; ni < 4; ni++) {
                int n = wn * 32 + ni * 8 + gid;
                int o = n * 40 + kk * 16 + tig * 2;
                bh2[ni][0] = *(const uint32_t*)&Bhb[o];
                bh2[ni][1] = *(const uint32_t*)&Bhb[o + 8];
                bl2[ni][0] = *(const uint32_t*)&Blb[o];
                bl2[ni][1] = *(const uint32_t*)&Blb[o + 8];
            }
#pragma unroll
            for (int mi = 0; mi < 2; mi++)
#pragma unroll
                for (int ni = 0; ni < 4; ni++) {
                    mma_bf16(c[mi][ni], al[mi], bh2[ni]);
                    mma_bf16(c[mi][ni], ah[mi], bl2[ni]);
                    mma_bf16(c[mi][ni], ah[mi], bh2[ni]);
                }
        }
        if (ch + 1 < T) {
            __syncthreads();
            __nv_bfloat16* Ahw = Ah + (cur ^ 1) * 5120;
            __nv_bfloat16* Alw = Al + (cur ^ 1) * 5120;
            __nv_bfloat16* Bhw = Bh + (cur ^ 1) * 2560;
            __nv_bfloat16* Blw = Bl + (cur ^ 1) * 2560;
#pragma unroll
            for (int i = 0; i < 4; i++) {
                int idx = t + i * 256, r = idx >> 3, kq = idx & 7;
                uint2 hp, lp;
                split4_pk(rA[i], hp, lp);
                *(uint2*)&Ahw[r * 40 + kq * 4] = hp;
                *(uint2*)&Alw[r * 40 + kq * 4] = lp;
            }
#pragma unroll
            for (int i = 0; i < 2; i++) {
                int idx = t + i * 256, sl = idx >> 4, dq = idx & 15;
                const float vv[4] = {rB[i].x, rB[i].y, rB[i].z, rB[i].w};
#pragma unroll
                for (int j = 0; j < 4; j++) {
                    __nv_bfloat16 hh, ll;
                    split1(vv[j], hh, ll);
                    Bhw[(dq * 4 + j) * 40 + sl] = hh;
                    Blw[(dq * 4 + j) * 40 + sl] = ll;
                }
            }
            __syncthreads();
        }
    }

#pragma unroll
    for (int mi = 0; mi < 2; mi++)
#pragma unroll
        for (int half = 0; half < 2; half++) {
            int s = q0 + wm * 32 + mi * 16 + gid + half * 8;
#pragma unroll
            for (int ni = 0; ni < 4; ni++) {
                int n = wn * 32 + ni * 8 + tig * 2;
                float2 v;
                v.x = c[mi][ni][half * 2 + 0];
                v.y = c[mi][ni][half * 2 + 1];
                *(float2*)&g_ctx[((size_t)(b * cS + s)) * cHS + h * cHD + n] = v;
            }
        }
}

// ===========================================================================
// Softmax over rows of attn (S=2048), float4 vectorized.
// ===========================================================================
__global__ __launch_bounds__(256)
void softmax_k(float* __restrict__ attn)
{
    const size_t row = blockIdx.x;
    float4* p = (float4*)(attn + row * cS);
    const int t = threadIdx.x;
    float4 v0 = p[t], v1 = p[t + 256];
    float mx = fmaxf(fmaxf(fmaxf(v0.x, v0.y), fmaxf(v0.z, v0.w)),
                     fmaxf(fmaxf(v1.x, v1.y), fmaxf(v1.z, v1.w)));
    __shared__ float red[8];
#pragma unroll
    for (int o = 16; o > 0; o >>= 1) mx = fmaxf(mx, __shfl_xor_sync(0xffffffff, mx, o));
    if ((t & 31) == 0) red[t >> 5] = mx;
    __syncthreads();
    mx = fmaxf(fmaxf(fmaxf(red[0], red[1]), fmaxf(red[2], red[3])),
               fmaxf(fmaxf(red[4], red[5]), fmaxf(red[6], red[7])));
    v0.x = __expf(v0.x - mx); v0.y = __expf(v0.y - mx);
    v0.z = __expf(v0.z - mx); v0.w = __expf(v0.w - mx);
    v1.x = __expf(v1.x - mx); v1.y = __expf(v1.y - mx);
    v1.z = __expf(v1.z - mx); v1.w = __expf(v1.w - mx);
    float sm = v0.x + v0.y + v0.z + v0.w + v1.x + v1.y + v1.z + v1.w;
#pragma unroll
    for (int o = 16; o > 0; o >>= 1) sm += __shfl_xor_sync(0xffffffff, sm, o);
    __shared__ float red2[8];
    if ((t & 31) == 0) red2[t >> 5] = sm;
    __syncthreads();
    sm = red2[0] + red2[1] + red2[2] + red2[3] + red2[4] + red2[5] + red2[6] + red2[7];
    float inv = 1.0f / sm;
    v0.x *= inv; v0.y *= inv; v0.z *= inv; v0.w *= inv;
    v1.x *= inv; v1.y *= inv; v1.z *= inv; v1.w *= inv;
    p[t] = v0; p[t + 256] = v1;
}

// ===========================================================================
// Weight transpose: g_WT[z][n][k] = W_z[k][n]
// ===========================================================================
__global__ void transpose_w(const float* __restrict__ W0, const float* __restrict__ W1,
                            const float* __restrict__ W2, const float* __restrict__ W3)
{
    __shared__ float tile[32][33];
    const float* W = blockIdx.z == 0 ? W0 : blockIdx.z == 1 ? W1 : blockIdx.z == 2 ? W2 : W3;
    float* O = g_WT + (size_t)blockIdx.z * cHS * cHS;
    int x = blockIdx.x * 32 + threadIdx.x;
    int y0 = blockIdx.y * 32;
#pragma unroll
    for (int i = 0; i < 4; i++)
        tile[threadIdx.y + i * 8][threadIdx.x] = W[(size_t)(y0 + threadIdx.y + i * 8) * cHS + x];
    __syncthreads();
    int nx = blockIdx.y * 32 + threadIdx.x;
    int ny0 = blockIdx.x * 32;
#pragma unroll
    for (int i = 0; i < 4; i++)
        O[(size_t)(ny0 + threadIdx.y + i * 8) * cHS + nx] = tile[threadIdx.x][threadIdx.y + i * 8];
}

// ===========================================================================
// Pattern selector (deterministic two-stage column mean)
// ===========================================================================
__global__ void qmean_partial(const float* __restrict__ query)
{
    const int b = blockIdx.y, tile = blockIdx.x;
    const int t = threadIdx.x;
    const int r0 = tile * 128;
    float s1 = 0.f, s2 = 0.f;
    for (int r = 0; r < 128; r++) {
        const float* base = query + ((size_t)b * cS + r0 + r) * cHS;
        s1 += base[t];
        s2 += base[t + 512];
    }
    g_qpart[(b * 16 + tile) * cHS + t] = s1;
    g_qpart[(b * 16 + tile) * cHS + t + 512] = s2;
}

__global__ __launch_bounds__(512)
void pattern_kernel(const float* __restrict__ Wp1, const float* __restrict__ bp1,
                    const float* __restrict__ Wp2, const float* __restrict__ bp2,
                    const float* __restrict__ patterns)
{
    const int b = blockIdx.x;
    const int t = threadIdx.x;
    __shared__ float qm[cHS];
    __shared__ float hb[cHS / 2];
    __shared__ float pw[cNP];
    for (int c = t; c < cHS; c += 512) {
        float s = 0.f;
        for (int p = 0; p < 16; p++) s += g_qpart[(b * 16 + p) * cHS + c];
        qm[c] = s * (1.0f / cS);
    }
    __syncthreads();
    {
        float a = bp1[t];
        for (int c = 0; c < cHS; c++) a += qm[c] * Wp1[c * (cHS / 2) + t];
        hb[t] = fmaxf(a, 0.f);
    }
    __syncthreads();
    __shared__ float lg[cNP];
    if (t < cNP) {
        float a = bp2[t];
        for (int j = 0; j < cHS / 2; j++) a += hb[j] * Wp2[j * cNP + t];
        lg[t] = a;
    }
    __syncthreads();
    if (t == 0) {
        float mx = lg[0];
        for (int p = 1; p < cNP; p++) mx = fmaxf(mx, lg[p]);
        float s = 0.f;
        for (int p = 0; p < cNP; p++) { pw[p] = __expf(lg[p] - mx); s += pw[p]; }
        float inv = 1.0f / s;
        for (int p = 0; p < cNP; p++) pw[p] *= inv;
    }
    __syncthreads();
    if (t < cNH) {
        float a = 0.f;
        for (int p = 0; p < cNP; p++) a += pw[p] * patterns[p * cNH + t];
        g_pat[b * cNH + t] = a;
    }
}

// ===========================================================================
// kernel_launch
// ===========================================================================
extern "C" void kernel_launch(void* const* d_in, const int* in_sizes, int n_in,
                              void* d_out, int out_size)
{
    const float* query = (const float*)d_in[0];
    const float* key   = (const float*)d_in[1];
    const float* value = (const float*)d_in[2];
    const int*   mask  = (const int*)d_in[3];
    const float* Wq  = (const float*)d_in[4];  const float* bq  = (const float*)d_in[5];
    const float* Wk  = (const float*)d_in[6];  const float* bk  = (const float*)d_in[7];
    const float* Wv  = (const float*)d_in[8];  const float* bv  = (const float*)d_in[9];
    const float* Wo  = (const float*)d_in[10]; const float* bo  = (const float*)d_in[11];
    const float* Wp1 = (const float*)d_in[12]; const float* bp1 = (const float*)d_in[13];
    const float* Wp2 = (const float*)d_in[14]; const float* bp2 = (const float*)d_in[15];
    const float* patterns = (const float*)d_in[16];
    float* out = (float*)d_out;

    void *pQ, *pK, *pV, *pCtx, *pWT;
    cudaGetSymbolAddress(&pQ, g_Q);
    cudaGetSymbolAddress(&pK, g_K);
    cudaGetSymbolAddress(&pV, g_V);
    cudaGetSymbolAddress(&pCtx, g_ctx);
    cudaGetSymbolAddress(&pWT, g_WT);
    const float* WT = (const float*)pWT;

    float* attn;
    if ((long)out_size >= OUT_ELEMS + ATTN_ELEMS) {
        attn = out + OUT_ELEMS;
    } else {
        void* pa;
        cudaGetSymbolAddress(&pa, g_attn_fallback);
        attn = (float*)pa;
    }

    const int SM_GEMM   = 8 * 5120 * 2;               // 81920
    const int SM_SCORES = 4 * 9216 * 2;               // 73728
    const int SM_CTX    = (4 * 5120 + 4 * 2560) * 2;  // 61440
    cudaFuncSetAttribute(gemm_bf<1>,  cudaFuncAttributeMaxDynamicSharedMemorySize, SM_GEMM);
    cudaFuncSetAttribute(gemm_bf<0>,  cudaFuncAttributeMaxDynamicSharedMemorySize, SM_GEMM);
    cudaFuncSetAttribute(scores_mma,  cudaFuncAttributeMaxDynamicSharedMemorySize, SM_SCORES);
    cudaFuncSetAttribute(context_mma, cudaFuncAttributeMaxDynamicSharedMemorySize, SM_CTX);

    // 1. pattern selector
    qmean_partial<<<dim3(16, cB), 512>>>(query);
    pattern_kernel<<<cB, 512>>>(Wp1, bp1, Wp2, bp2, patterns);

    // 2. transpose weights (Wq, Wk, Wv, Wo)
    transpose_w<<<dim3(32, 32, 4), dim3(32, 8)>>>(Wq, Wk, Wv, Wo);

    // 3. merged QKV projection -> [B,NH,S,HD]
    dim3 gProj(cHS / 128, (cB * cS) / 128, 3);  // (8, 32, 3)
    gemm_bf<1><<<gProj, 256, SM_GEMM>>>(query, key, value, WT, bq, bk, bv,
                                        (float*)pQ, (float*)pK, (float*)pV);

    // 4. scores
    dim3 gScores(cS / 128, cS / 128, cB * cNH);  // (16, 16, 32)
    scores_mma<<<gScores, 256, SM_SCORES>>>(mask, attn);

    // 5. softmax
    softmax_k<<<cB * cNH * cS, 256>>>(attn);

    // 6. context
    dim3 gCtx(cS / 128, cB * cNH);  // (16, 32)
    context_mma<<<gCtx, 256, SM_CTX>>>(attn);

    // 7. output projection
    dim3 gOut(cHS / 128, (cB * cS) / 128, 1);
    gemm_bf<0><<<gOut, 256, SM_GEMM>>>((const float*)pCtx, nullptr, nullptr,
                                       WT + 3L * cHS * cHS, bo, nullptr, nullptr,
                                       out, nullptr, nullptr);
}

// round 9
// speedup vs baseline: 1.4635x; 1.0738x over previous
#include <cuda_runtime.h>
#include <cuda_bf16.h>
#include <cstdint>
#include <math_constants.h>

// ---------------------------------------------------------------------------
// AdaptiveAttention: B=2, S=2048, HS=1024, NH=16, HD=64, NP=8
// Round 9: fused softmax — scores emits LSE partials, context applies
//          exp-normalize in-register and overwrites raw scores with p.
// ---------------------------------------------------------------------------

constexpr int cB = 2, cS = 2048, cHS = 1024, cNH = 16, cNP = 8, cHD = 64;
constexpr float cSCALE = 0.125f;  // 1/sqrt(64)
constexpr long OUT_ELEMS  = (long)cB * cS * cHS;        // 4,194,304
constexpr long ATTN_ELEMS = (long)cB * cNH * cS * cS;   // 134,217,728

__device__ float g_Q[(long)cB * cNH * cS * cHD];
__device__ float g_K[(long)cB * cNH * cS * cHD];
__device__ float g_V[(long)cB * cNH * cS * cHD];     // [b,h,s,d]
__device__ float g_ctx[(long)cB * cS * cHS];
__device__ float g_pat[cB * cNH];
__device__ float g_WT[4L * cHS * cHS];               // transposed weights [N,K] x4
__device__ float g_qpart[32 * cHS];
__device__ float2 g_pstats[(long)cB * cNH * cS * 16];   // per (bh,q,ktile) partial (m, sumexp)
__device__ float2 g_rowstats[(long)cB * cNH * cS];      // per (bh,q) (M, 1/S)
__device__ float g_attn_fallback[ATTN_ELEMS];

// ---------------------------------------------------------------------------
__device__ __forceinline__ void mma_bf16(float c[4], const uint32_t a[4], const uint32_t b[2]) {
    asm volatile(
        "mma.sync.aligned.m16n8k16.row.col.f32.bf16.bf16.f32 "
        "{%0,%1,%2,%3}, {%4,%5,%6,%7}, {%8,%9}, {%0,%1,%2,%3};"
        : "+f"(c[0]), "+f"(c[1]), "+f"(c[2]), "+f"(c[3])
        : "r"(a[0]), "r"(a[1]), "r"(a[2]), "r"(a[3]), "r"(b[0]), "r"(b[1]));
}

__device__ __forceinline__ uint32_t pk2(__nv_bfloat16 a, __nv_bfloat16 b) {
    __nv_bfloat162 t;
    t.x = a; t.y = b;
    return *(uint32_t*)&t;
}

__device__ __forceinline__ void split4_pk(float4 v, uint2& hp, uint2& lp) {
    __nv_bfloat16 h0 = __float2bfloat16_rn(v.x);
    __nv_bfloat16 h1 = __float2bfloat16_rn(v.y);
    __nv_bfloat16 h2 = __float2bfloat16_rn(v.z);
    __nv_bfloat16 h3 = __float2bfloat16_rn(v.w);
    __nv_bfloat16 l0 = __float2bfloat16_rn(v.x - __bfloat162float(h0));
    __nv_bfloat16 l1 = __float2bfloat16_rn(v.y - __bfloat162float(h1));
    __nv_bfloat16 l2 = __float2bfloat16_rn(v.z - __bfloat162float(h2));
    __nv_bfloat16 l3 = __float2bfloat16_rn(v.w - __bfloat162float(h3));
    hp.x = pk2(h0, h1); hp.y = pk2(h2, h3);
    lp.x = pk2(l0, l1); lp.y = pk2(l2, l3);
}

__device__ __forceinline__ void split1(float x, __nv_bfloat16& h, __nv_bfloat16& l) {
    h = __float2bfloat16_rn(x);
    l = __float2bfloat16_rn(x - __bfloat162float(h));
}

// ===========================================================================
// gemm_bf: C = A[4096,1024] @ Bt^T + bias (Bt is [N,K]).
// MODE 1: merged QKV via blockIdx.z, scatter to [B,NH,S,HD].
// MODE 0: single GEMM, row-major store.
// ===========================================================================
template <int MODE>
__global__ __launch_bounds__(256)
void gemm_bf(const float* __restrict__ A0, const float* __restrict__ A1,
             const float* __restrict__ A2, const float* __restrict__ WT,
             const float* __restrict__ b0v, const float* __restrict__ b1v,
             const float* __restrict__ b2v,
             float* __restrict__ C0, float* __restrict__ C1, float* __restrict__ C2)
{
    extern __shared__ char smraw[];
    __nv_bfloat16* Ah = (__nv_bfloat16*)smraw;        // [2][128*40]
    __nv_bfloat16* Al = Ah + 2 * 5120;
    __nv_bfloat16* Bh = Ah + 4 * 5120;
    __nv_bfloat16* Bl = Ah + 6 * 5120;
    const int z = (MODE == 1) ? blockIdx.z : 0;
    const float* A    = z == 0 ? A0 : (z == 1 ? A1 : A2);
    const float* Bt   = WT + (size_t)z * cHS * cHS;
    const float* bias = z == 0 ? b0v : (z == 1 ? b1v : b2v);
    float* C          = z == 0 ? C0 : (z == 1 ? C1 : C2);

    const int t = threadIdx.x, lane = t & 31, wid = t >> 5;
    const int wm = wid >> 1, wn = wid & 1;
    const int gid = lane >> 2, tig = lane & 3;
    const int m0 = blockIdx.y * 128, n0 = blockIdx.x * 128;

    float c[2][8][4] = {};
    float4 rA[4], rB[4];

#pragma unroll
    for (int i = 0; i < 4; i++) {
        int idx = t + i * 256, r = idx >> 3, kq = idx & 7;
        rA[i] = *(const float4*)&A[(size_t)(m0 + r) * 1024 + kq * 4];
        rB[i] = *(const float4*)&Bt[(size_t)(n0 + r) * 1024 + kq * 4];
    }
#pragma unroll
    for (int i = 0; i < 4; i++) {
        int idx = t + i * 256, r = idx >> 3, kq = idx & 7;
        uint2 hp, lp;
        split4_pk(rA[i], hp, lp);
        *(uint2*)&Ah[r * 40 + kq * 4] = hp;
        *(uint2*)&Al[r * 40 + kq * 4] = lp;
        split4_pk(rB[i], hp, lp);
        *(uint2*)&Bh[r * 40 + kq * 4] = hp;
        *(uint2*)&Bl[r * 40 + kq * 4] = lp;
    }
    __syncthreads();

    const int T = 32;
    for (int ch = 0; ch < T; ch++) {
        const int cur = ch & 1;
        if (ch + 1 < T) {
#pragma unroll
            for (int i = 0; i < 4; i++) {
                int idx = t + i * 256, r = idx >> 3, kq = idx & 7;
                rA[i] = *(const float4*)&A[(size_t)(m0 + r) * 1024 + (ch + 1) * 32 + kq * 4];
                rB[i] = *(const float4*)&Bt[(size_t)(n0 + r) * 1024 + (ch + 1) * 32 + kq * 4];
            }
        }
        const __nv_bfloat16* Ahb = Ah + cur * 5120;
        const __nv_bfloat16* Alb = Al + cur * 5120;
        const __nv_bfloat16* Bhb = Bh + cur * 5120;
        const __nv_bfloat16* Blb = Bl + cur * 5120;
#pragma unroll
        for (int kk = 0; kk < 2; kk++) {
            uint32_t ah[2][4], al[2][4], bh[8][2], bl[8][2];
#pragma unroll
            for (int mi = 0; mi < 2; mi++) {
                int r = wm * 32 + mi * 16 + gid;
                int o = r * 40 + kk * 16 + tig * 2;
                ah[mi][0] = *(const uint32_t*)&Ahb[o];
                ah[mi][1] = *(const uint32_t*)&Ahb[o + 320];
                ah[mi][2] = *(const uint32_t*)&Ahb[o + 8];
                ah[mi][3] = *(const uint32_t*)&Ahb[o + 328];
                al[mi][0] = *(const uint32_t*)&Alb[o];
                al[mi][1] = *(const uint32_t*)&Alb[o + 320];
                al[mi][2] = *(const uint32_t*)&Alb[o + 8];
                al[mi][3] = *(const uint32_t*)&Alb[o + 328];
            }
#pragma unroll
            for (int ni = 0; ni < 8; ni++) {
                int n = wn * 64 + ni * 8 + gid;
                int o = n * 40 + kk * 16 + tig * 2;
                bh[ni][0] = *(const uint32_t*)&Bhb[o];
                bh[ni][1] = *(const uint32_t*)&Bhb[o + 8];
                bl[ni][0] = *(const uint32_t*)&Blb[o];
                bl[ni][1] = *(const uint32_t*)&Blb[o + 8];
            }
#pragma unroll
            for (int mi = 0; mi < 2; mi++)
#pragma unroll
                for (int ni = 0; ni < 8; ni++) {
                    mma_bf16(c[mi][ni], al[mi], bh[ni]);
                    mma_bf16(c[mi][ni], ah[mi], bl[ni]);
                    mma_bf16(c[mi][ni], ah[mi], bh[ni]);
                }
        }
        if (ch + 1 < T) {
            __syncthreads();
            __nv_bfloat16* Ahw = Ah + (cur ^ 1) * 5120;
            __nv_bfloat16* Alw = Al + (cur ^ 1) * 5120;
            __nv_bfloat16* Bhw = Bh + (cur ^ 1) * 5120;
            __nv_bfloat16* Blw = Bl + (cur ^ 1) * 5120;
#pragma unroll
            for (int i = 0; i < 4; i++) {
                int idx = t + i * 256, r = idx >> 3, kq = idx & 7;
                uint2 hp, lp;
                split4_pk(rA[i], hp, lp);
                *(uint2*)&Ahw[r * 40 + kq * 4] = hp;
                *(uint2*)&Alw[r * 40 + kq * 4] = lp;
                split4_pk(rB[i], hp, lp);
                *(uint2*)&Bhw[r * 40 + kq * 4] = hp;
                *(uint2*)&Blw[r * 40 + kq * 4] = lp;
            }
            __syncthreads();
        }
    }

#pragma unroll
    for (int mi = 0; mi < 2; mi++)
#pragma unroll
        for (int half = 0; half < 2; half++) {
            int m = m0 + wm * 32 + mi * 16 + gid + half * 8;
            int b = m >> 11, s = m & 2047;
#pragma unroll
            for (int ni = 0; ni < 8; ni++) {
                int n = n0 + wn * 64 + ni * 8 + tig * 2;
                float2 v;
                v.x = c[mi][ni][half * 2 + 0] + bias[n];
                v.y = c[mi][ni][half * 2 + 1] + bias[n + 1];
                if (MODE == 0) {
                    *(float2*)&C[(size_t)m * 1024 + n] = v;
                } else {
                    int h = n >> 6, d = n & 63;
                    *(float2*)&C[(((size_t)(b * cNH + h) * cS + s) * cHD) + d] = v;
                }
            }
        }
}

// ===========================================================================
// scores_mma: raw[bh,q,k] = (Q.K)*SCALE*pat, masked — written raw; also emits
// per-(row, ktile) LSE partials (m, sumexp) to g_pstats.
// ===========================================================================
__global__ __launch_bounds__(256)
void scores_mma(const int* __restrict__ mask, float* __restrict__ attn)
{
    extern __shared__ char smraw[];
    __nv_bfloat16* Qh = (__nv_bfloat16*)smraw;    // 128*72 each
    __nv_bfloat16* Ql = Qh + 9216;
    __nv_bfloat16* Kh = Qh + 2 * 9216;
    __nv_bfloat16* Kl = Qh + 3 * 9216;
    __shared__ float s_m[128][2];
    __shared__ float s_s[128][2];
    const int t = threadIdx.x, lane = t & 31, wid = t >> 5;
    const int wm = wid >> 1, wn = wid & 1;
    const int gid = lane >> 2, tig = lane & 3;
    const int bh = blockIdx.z, b = bh >> 4;
    const int q0 = blockIdx.y * 128, n0 = blockIdx.x * 128;
    const float* Qm = g_Q + (size_t)bh * cS * cHD;
    const float* Km = g_K + (size_t)bh * cS * cHD;

#pragma unroll
    for (int i = 0; i < 8; i++) {
        int idx = t + i * 256, r = idx >> 4, kq = idx & 15;
        uint2 hp, lp;
        float4 v = *(const float4*)&Qm[(size_t)(q0 + r) * 64 + kq * 4];
        split4_pk(v, hp, lp);
        *(uint2*)&Qh[r * 72 + kq * 4] = hp;
        *(uint2*)&Ql[r * 72 + kq * 4] = lp;
        v = *(const float4*)&Km[(size_t)(n0 + r) * 64 + kq * 4];
        split4_pk(v, hp, lp);
        *(uint2*)&Kh[r * 72 + kq * 4] = hp;
        *(uint2*)&Kl[r * 72 + kq * 4] = lp;
    }
    __syncthreads();

    float c[2][8][4] = {};
#pragma unroll
    for (int kk = 0; kk < 4; kk++) {
        uint32_t ah[2][4], al[2][4], bh2[8][2], bl2[8][2];
#pragma unroll
        for (int mi = 0; mi < 2; mi++) {
            int r = wm * 32 + mi * 16 + gid;
            int o = r * 72 + kk * 16 + tig * 2;
            ah[mi][0] = *(const uint32_t*)&Qh[o];
            ah[mi][1] = *(const uint32_t*)&Qh[o + 576];
            ah[mi][2] = *(const uint32_t*)&Qh[o + 8];
            ah[mi][3] = *(const uint32_t*)&Qh[o + 584];
            al[mi][0] = *(const uint32_t*)&Ql[o];
            al[mi][1] = *(const uint32_t*)&Ql[o + 576];
            al[mi][2] = *(const uint32_t*)&Ql[o + 8];
            al[mi][3] = *(const uint32_t*)&Ql[o + 584];
        }
#pragma unroll
        for (int ni = 0; ni < 8; ni++) {
            int n = wn * 64 + ni * 8 + gid;
            int o = n * 72 + kk * 16 + tig * 2;
            bh2[ni][0] = *(const uint32_t*)&Kh[o];
            bh2[ni][1] = *(const uint32_t*)&Kh[o + 8];
            bl2[ni][0] = *(const uint32_t*)&Kl[o];
            bl2[ni][1] = *(const uint32_t*)&Kl[o + 8];
        }
#pragma unroll
        for (int mi = 0; mi < 2; mi++)
#pragma unroll
            for (int ni = 0; ni < 8; ni++) {
                mma_bf16(c[mi][ni], al[mi], bh2[ni]);
                mma_bf16(c[mi][ni], ah[mi], bl2[ni]);
                mma_bf16(c[mi][ni], ah[mi], bh2[ni]);
            }
    }

    const float patv = g_pat[bh] * cSCALE;
    const size_t mbase = (size_t)b * cS * cS;
    const size_t abase = (size_t)bh * cS * cS;
#pragma unroll
    for (int mi = 0; mi < 2; mi++)
#pragma unroll
        for (int half = 0; half < 2; half++) {
            int lr = wm * 32 + mi * 16 + half * 8 + gid;
            int q = q0 + lr;
            float vals[16];
            float mx = -CUDART_INF_F;
#pragma unroll
            for (int ni = 0; ni < 8; ni++) {
                int col = n0 + wn * 64 + ni * 8 + tig * 2;
                float2 v;
                v.x = c[mi][ni][half * 2 + 0] * patv;
                v.y = c[mi][ni][half * 2 + 1] * patv;
                int2 mk = *(const int2*)&mask[mbase + (size_t)q * cS + col];
                if (mk.x == 0) v.x = -1e9f;
                if (mk.y == 0) v.y = -1e9f;
                *(float2*)&attn[abase + (size_t)q * cS + col] = v;
                vals[ni * 2] = v.x; vals[ni * 2 + 1] = v.y;
                mx = fmaxf(mx, fmaxf(v.x, v.y));
            }
            mx = fmaxf(mx, __shfl_xor_sync(0xffffffff, mx, 1));
            mx = fmaxf(mx, __shfl_xor_sync(0xffffffff, mx, 2));
            float s = 0.f;
#pragma unroll
            for (int j = 0; j < 16; j++) s += __expf(vals[j] - mx);
            s += __shfl_xor_sync(0xffffffff, s, 1);
            s += __shfl_xor_sync(0xffffffff, s, 2);
            if (tig == 0) { s_m[lr][wn] = mx; s_s[lr][wn] = s; }
        }
    __syncthreads();
    if (t < 128) {
        float m0v = s_m[t][0], m1v = s_m[t][1];
        float s0v = s_s[t][0], s1v = s_s[t][1];
        float M = fmaxf(m0v, m1v);
        float S = s0v * __expf(m0v - M) + s1v * __expf(m1v - M);
        g_pstats[((size_t)bh * cS + q0 + t) * 16 + blockIdx.x] = make_float2(M, S);
    }
}

// ===========================================================================
// merge_stats: per-row LSE merge of 16 partials -> (M, 1/S)
// ===========================================================================
__global__ __launch_bounds__(256)
void merge_stats()
{
    const int idx = blockIdx.x * 256 + threadIdx.x;  // 0 .. 65535
    const float2* ps = &g_pstats[(size_t)idx * 16];
    float M = -CUDART_INF_F;
#pragma unroll
    for (int j = 0; j < 16; j++) M = fmaxf(M, ps[j].x);
    float S = 0.f;
#pragma unroll
    for (int j = 0; j < 16; j++) S += ps[j].y * __expf(ps[j].x - M);
    g_rowstats[idx] = make_float2(M, 1.0f / S);
}

// ===========================================================================
// context_mma (fused softmax): reads raw scores, p = exp(s-M)/S, writes p
// back in place, accumulates p @ V. Block 128x64, K=2048.
// ===========================================================================
__global__ __launch_bounds__(256)
void context_mma(float* attn)
{
    extern __shared__ char smraw[];
    __nv_bfloat16* Ah = (__nv_bfloat16*)smraw;   // [2][128*40]
    __nv_bfloat16* Al = Ah + 2 * 5120;
    __nv_bfloat16* Bh = Ah + 4 * 5120;           // [2][64*40]
    __nv_bfloat16* Bl = Ah + 4 * 5120 + 2 * 2560;
    __shared__ float sm_m[128], sm_i[128];
    const int t = threadIdx.x, lane = t & 31, wid = t >> 5;
    const int wm = wid >> 1, wn = wid & 1;
    const int gid = lane >> 2, tig = lane & 3;
    const int bh = blockIdx.y, q0 = blockIdx.x * 128;
    const int b = bh >> 4, h = bh & 15;
    float* Am = attn + (size_t)bh * cS * cS;
    const float* Vm = g_V + (size_t)bh * cS * cHD;

    if (t < 128) {
        float2 rs = g_rowstats[(size_t)bh * cS + q0 + t];
        sm_m[t] = rs.x; sm_i[t] = rs.y;
    }

    float c[2][4][4] = {};
    float4 rA[4], rB[2];

#pragma unroll
    for (int i = 0; i < 4; i++) {
        int idx = t + i * 256, r = idx >> 3, kq = idx & 7;
        rA[i] = *(const float4*)&Am[(size_t)(q0 + r) * cS + kq * 4];
    }
#pragma unroll
    for (int i = 0; i < 2; i++) {
        int idx = t + i * 256, sl = idx >> 4, dq = idx & 15;
        rB[i] = *(const float4*)&Vm[(size_t)sl * 64 + dq * 4];
    }
    __syncthreads();  // sm_m/sm_i visible
#pragma unroll
    for (int i = 0; i < 4; i++) {
        int idx = t + i * 256, r = idx >> 3, kq = idx & 7;
        float mm = sm_m[r], ii = sm_i[r];
        float4 p;
        p.x = __expf(rA[i].x - mm) * ii;
        p.y = __expf(rA[i].y - mm) * ii;
        p.z = __expf(rA[i].z - mm) * ii;
        p.w = __expf(rA[i].w - mm) * ii;
        *(float4*)&Am[(size_t)(q0 + r) * cS + kq * 4] = p;
        uint2 hp, lp;
        split4_pk(p, hp, lp);
        *(uint2*)&Ah[r * 40 + kq * 4] = hp;
        *(uint2*)&Al[r * 40 + kq * 4] = lp;
    }
#pragma unroll
    for (int i = 0; i < 2; i++) {
        int idx = t + i * 256, sl = idx >> 4, dq = idx & 15;
        const float vv[4] = {rB[i].x, rB[i].y, rB[i].z, rB[i].w};
#pragma unroll
        for (int j = 0; j < 4; j++) {
            __nv_bfloat16 hh, ll;
            split1(vv[j], hh, ll);
            Bh[(dq * 4 + j) * 40 + sl] = hh;
            Bl[(dq * 4 + j) * 40 + sl] = ll;
        }
    }
    __syncthreads();

    const int T = 64;
    for (int ch = 0; ch < T; ch++) {
        const int cur = ch & 1;
        if (ch + 1 < T) {
#pragma unroll
            for (int i = 0; i < 4; i++) {
                int idx = t + i * 256, r = idx >> 3, kq = idx & 7;
                rA[i] = *(const float4*)&Am[(size_t)(q0 + r) * cS + (ch + 1) * 32 + kq * 4];
            }
#pragma unroll
            for (int i = 0; i < 2; i++) {
                int idx = t + i * 256, sl = idx >> 4, dq = idx & 15;
                rB[i] = *(const float4*)&Vm[(size_t)((ch + 1) * 32 + sl) * 64 + dq * 4];
            }
        }
        const __nv_bfloat16* Ahb = Ah + cur * 5120;
        const __nv_bfloat16* Alb = Al + cur * 5120;
        const __nv_bfloat16* Bhb = Bh + cur * 2560;
        const __nv_bfloat16* Blb = Bl + cur * 2560;
#pragma unroll
        for (int kk = 0; kk < 2; kk++) {
            uint32_t ah[2][4], al[2][4], bh2[4][2], bl2[4][2];
#pragma unroll
            for (int mi = 0; mi < 2; mi++) {
                int r = wm * 32 + mi * 16 + gid;
                int o = r * 40 + kk * 16 + tig * 2;
                ah[mi][0] = *(const uint32_t*)&Ahb[o];
                ah[mi][1] = *(const uint32_t*)&Ahb[o + 320];
                ah[mi][2] = *(const uint32_t*)&Ahb[o + 8];
                ah[mi][3] = *(const uint32_t*)&Ahb[o + 328];
                al[mi][0] = *(const uint32_t*)&Alb[o];
                al[mi][1] = *(const uint32_t*)&Alb[o + 320];
                al[mi][2] = *(const uint32_t*)&Alb[o + 8];
                al[mi][3] = *(const uint32_t*)&Alb[o + 328];
            }
#pragma unroll
            for (int ni = 0; ni < 4; ni++) {
                int n = wn * 32 + ni * 8 + gid;
                int o = n * 40 + kk * 16 + tig * 2;
                bh2[ni][0] = *(const uint32_t*)&Bhb[o];
                bh2[ni][1] = *(const uint32_t*)&Bhb[o + 8];
                bl2[ni][0] = *(const uint32_t*)&Blb[o];
                bl2[ni][1] = *(const uint32_t*)&Blb[o + 8];
            }
#pragma unroll
            for (int mi = 0; mi < 2; mi++)
#pragma unroll
                for (int ni = 0; ni < 4; ni++) {
                    mma_bf16(c[mi][ni], al[mi], bh2[ni]);
                    mma_bf16(c[mi][ni], ah[mi], bl2[ni]);
                    mma_bf16(c[mi][ni], ah[mi], bh2[ni]);
                }
        }
        if (ch + 1 < T) {
            __syncthreads();
            __nv_bfloat16* Ahw = Ah + (cur ^ 1) * 5120;
            __nv_bfloat16* Alw = Al + (cur ^ 1) * 5120;
            __nv_bfloat16* Bhw = Bh + (cur ^ 1) * 2560;
            __nv_bfloat16* Blw = Bl + (cur ^ 1) * 2560;
#pragma unroll
            for (int i = 0; i < 4; i++) {
                int idx = t + i * 256, r = idx >> 3, kq = idx & 7;
                float mm = sm_m[r], ii = sm_i[r];
                float4 p;
                p.x = __expf(rA[i].x - mm) * ii;
                p.y = __expf(rA[i].y - mm) * ii;
                p.z = __expf(rA[i].z - mm) * ii;
                p.w = __expf(rA[i].w - mm) * ii;
                *(float4*)&Am[(size_t)(q0 + r) * cS + (ch + 1) * 32 + kq * 4] = p;
                uint2 hp, lp;
                split4_pk(p, hp, lp);
                *(uint2*)&Ahw[r * 40 + kq * 4] = hp;
                *(uint2*)&Alw[r * 40 + kq * 4] = lp;
            }
#pragma unroll
            for (int i = 0; i < 2; i++) {
                int idx = t + i * 256, sl = idx >> 4, dq = idx & 15;
                const float vv[4] = {rB[i].x, rB[i].y, rB[i].z, rB[i].w};
#pragma unroll
                for (int j = 0; j < 4; j++) {
                    __nv_bfloat16 hh, ll;
                    split1(vv[j], hh, ll);
                    Bhw[(dq * 4 + j) * 40 + sl] = hh;
                    Blw[(dq * 4 + j) * 40 + sl] = ll;
                }
            }
            __syncthreads();
        }
    }

#pragma unroll
    for (int mi = 0; mi < 2; mi++)
#pragma unroll
        for (int half = 0; half < 2; half++) {
            int s = q0 + wm * 32 + mi * 16 + gid + half * 8;
#pragma unroll
            for (int ni = 0; ni < 4; ni++) {
                int n = wn * 32 + ni * 8 + tig * 2;
                float2 v;
                v.x = c[mi][ni][half * 2 + 0];
                v.y = c[mi][ni][half * 2 + 1];
                *(float2*)&g_ctx[((size_t)(b * cS + s)) * cHS + h * cHD + n] = v;
            }
        }
}

// ===========================================================================
// Weight transpose: g_WT[z][n][k] = W_z[k][n]
// ===========================================================================
__global__ void transpose_w(const float* __restrict__ W0, const float* __restrict__ W1,
                            const float* __restrict__ W2, const float* __restrict__ W3)
{
    __shared__ float tile[32][33];
    const float* W = blockIdx.z == 0 ? W0 : blockIdx.z == 1 ? W1 : blockIdx.z == 2 ? W2 : W3;
    float* O = g_WT + (size_t)blockIdx.z * cHS * cHS;
    int x = blockIdx.x * 32 + threadIdx.x;
    int y0 = blockIdx.y * 32;
#pragma unroll
    for (int i = 0; i < 4; i++)
        tile[threadIdx.y + i * 8][threadIdx.x] = W[(size_t)(y0 + threadIdx.y + i * 8) * cHS + x];
    __syncthreads();
    int nx = blockIdx.y * 32 + threadIdx.x;
    int ny0 = blockIdx.x * 32;
#pragma unroll
    for (int i = 0; i < 4; i++)
        O[(size_t)(ny0 + threadIdx.y + i * 8) * cHS + nx] = tile[threadIdx.x][threadIdx.y + i * 8];
}

// ===========================================================================
// Pattern selector (deterministic two-stage column mean)
// ===========================================================================
__global__ void qmean_partial(const float* __restrict__ query)
{
    const int b = blockIdx.y, tile = blockIdx.x;
    const int t = threadIdx.x;
    const int r0 = tile * 128;
    float s1 = 0.f, s2 = 0.f;
    for (int r = 0; r < 128; r++) {
        const float* base = query + ((size_t)b * cS + r0 + r) * cHS;
        s1 += base[t];
        s2 += base[t + 512];
    }
    g_qpart[(b * 16 + tile) * cHS + t] = s1;
    g_qpart[(b * 16 + tile) * cHS + t + 512] = s2;
}

__global__ __launch_bounds__(512)
void pattern_kernel(const float* __restrict__ Wp1, const float* __restrict__ bp1,
                    const float* __restrict__ Wp2, const float* __restrict__ bp2,
                    const float* __restrict__ patterns)
{
    const int b = blockIdx.x;
    const int t = threadIdx.x;
    __shared__ float qm[cHS];
    __shared__ float hb[cHS / 2];
    __shared__ float pw[cNP];
    for (int c = t; c < cHS; c += 512) {
        float s = 0.f;
        for (int p = 0; p < 16; p++) s += g_qpart[(b * 16 + p) * cHS + c];
        qm[c] = s * (1.0f / cS);
    }
    __syncthreads();
    {
        float a = bp1[t];
        for (int c = 0; c < cHS; c++) a += qm[c] * Wp1[c * (cHS / 2) + t];
        hb[t] = fmaxf(a, 0.f);
    }
    __syncthreads();
    __shared__ float lg[cNP];
    if (t < cNP) {
        float a = bp2[t];
        for (int j = 0; j < cHS / 2; j++) a += hb[j] * Wp2[j * cNP + t];
        lg[t] = a;
    }
    __syncthreads();
    if (t == 0) {
        float mx = lg[0];
        for (int p = 1; p < cNP; p++) mx = fmaxf(mx, lg[p]);
        float s = 0.f;
        for (int p = 0; p < cNP; p++) { pw[p] = __expf(lg[p] - mx); s += pw[p]; }
        float inv = 1.0f / s;
        for (int p = 0; p < cNP; p++) pw[p] *= inv;
    }
    __syncthreads();
    if (t < cNH) {
        float a = 0.f;
        for (int p = 0; p < cNP; p++) a += pw[p] * patterns[p * cNH + t];
        g_pat[b * cNH + t] = a;
    }
}

// ===========================================================================
// kernel_launch
// ===========================================================================
extern "C" void kernel_launch(void* const* d_in, const int* in_sizes, int n_in,
                              void* d_out, int out_size)
{
    const float* query = (const float*)d_in[0];
    const float* key   = (const float*)d_in[1];
    const float* value = (const float*)d_in[2];
    const int*   mask  = (const int*)d_in[3];
    const float* Wq  = (const float*)d_in[4];  const float* bq  = (const float*)d_in[5];
    const float* Wk  = (const float*)d_in[6];  const float* bk  = (const float*)d_in[7];
    const float* Wv  = (const float*)d_in[8];  const float* bv  = (const float*)d_in[9];
    const float* Wo  = (const float*)d_in[10]; const float* bo  = (const float*)d_in[11];
    const float* Wp1 = (const float*)d_in[12]; const float* bp1 = (const float*)d_in[13];
    const float* Wp2 = (const float*)d_in[14]; const float* bp2 = (const float*)d_in[15];
    const float* patterns = (const float*)d_in[16];
    float* out = (float*)d_out;

    void *pQ, *pK, *pV, *pCtx, *pWT;
    cudaGetSymbolAddress(&pQ, g_Q);
    cudaGetSymbolAddress(&pK, g_K);
    cudaGetSymbolAddress(&pV, g_V);
    cudaGetSymbolAddress(&pCtx, g_ctx);
    cudaGetSymbolAddress(&pWT, g_WT);
    const float* WT = (const float*)pWT;

    float* attn;
    if ((long)out_size >= OUT_ELEMS + ATTN_ELEMS) {
        attn = out + OUT_ELEMS;
    } else {
        void* pa;
        cudaGetSymbolAddress(&pa, g_attn_fallback);
        attn = (float*)pa;
    }

    const int SM_GEMM   = 8 * 5120 * 2;               // 81920
    const int SM_SCORES = 4 * 9216 * 2;               // 73728
    const int SM_CTX    = (4 * 5120 + 4 * 2560) * 2;  // 61440
    cudaFuncSetAttribute(gemm_bf<1>,  cudaFuncAttributeMaxDynamicSharedMemorySize, SM_GEMM);
    cudaFuncSetAttribute(gemm_bf<0>,  cudaFuncAttributeMaxDynamicSharedMemorySize, SM_GEMM);
    cudaFuncSetAttribute(scores_mma,  cudaFuncAttributeMaxDynamicSharedMemorySize, SM_SCORES);
    cudaFuncSetAttribute(context_mma, cudaFuncAttributeMaxDynamicSharedMemorySize, SM_CTX);

    // 1. pattern selector
    qmean_partial<<<dim3(16, cB), 512>>>(query);
    pattern_kernel<<<cB, 512>>>(Wp1, bp1, Wp2, bp2, patterns);

    // 2. transpose weights (Wq, Wk, Wv, Wo)
    transpose_w<<<dim3(32, 32, 4), dim3(32, 8)>>>(Wq, Wk, Wv, Wo);

    // 3. merged QKV projection -> [B,NH,S,HD]
    dim3 gProj(cHS / 128, (cB * cS) / 128, 3);  // (8, 32, 3)
    gemm_bf<1><<<gProj, 256, SM_GEMM>>>(query, key, value, WT, bq, bk, bv,
                                        (float*)pQ, (float*)pK, (float*)pV);

    // 4. raw scores + LSE partials
    dim3 gScores(cS / 128, cS / 128, cB * cNH);  // (16, 16, 32)
    scores_mma<<<gScores, 256, SM_SCORES>>>(mask, attn);

    // 5. merge row stats
    merge_stats<<<(cB * cNH * cS) / 256, 256>>>();

    // 6. fused softmax + context (overwrites raw scores with p in place)
    dim3 gCtx(cS / 128, cB * cNH);  // (16, 32)
    context_mma<<<gCtx, 256, SM_CTX>>>(attn);

    // 7. output projection
    dim3 gOut(cHS / 128, (cB * cS) / 128, 1);
    gemm_bf<0><<<gOut, 256, SM_GEMM>>>((const float*)pCtx, nullptr, nullptr,
                                       WT + 3L * cHS * cHS, bo, nullptr, nullptr,
                                       out, nullptr, nullptr);
}